// round 1
// baseline (speedup 1.0000x reference)
#include <cuda_runtime.h>
#include <math.h>
#include <stdint.h>

#define BATCH    2
#define SEQ      1024
#define DIMM     1024
#define D_STATE  64
#define D_CONV   4
#define N_HEADS  8
#define D_INNER  2048
#define HEAD_DIM 256
#define D_IN_PROJ 4232          // 2048 + 2048 + 8 + 64 + 64
#define ML       (BATCH*SEQ)    // 2048

// ---------------- scratch (device globals: allocation-free) ----------------
__device__ float g_zx[(size_t)ML * D_IN_PROJ];      // in_proj output
__device__ float g_xconv[(size_t)ML * D_INNER];     // silu(conv(xc)) == xh
__device__ float g_y[(size_t)ML * D_INNER];         // y*silu(z), then normed
__device__ float g_abar[ML * N_HEADS];

// ---------------- generic NT SGEMM: C[m,n] = sum_k A[m,k]*B[n,k] ------------
// A row-major [M,K], B row-major [N,K], C row-major [M,N].
// BM=BN=128, BK=16, 256 threads, 8x8 per thread (split 4+4 register tiles).
__global__ __launch_bounds__(256) void gemm_nt_kernel(
    const float* __restrict__ A, const float* __restrict__ B,
    float* __restrict__ C, int M, int N, int K)
{
    __shared__ float As[16][128];
    __shared__ float Bs[16][128];

    const int tid = threadIdx.x;
    const int bm = blockIdx.y * 128;
    const int bn = blockIdx.x * 128;
    const int tx = tid & 15;   // 16 cols of threads
    const int ty = tid >> 4;   // 16 rows of threads

    float acc[8][8];
#pragma unroll
    for (int i = 0; i < 8; i++)
#pragma unroll
        for (int j = 0; j < 8; j++) acc[i][j] = 0.f;

    for (int k0 = 0; k0 < K; k0 += 16) {
        // load A tile: 128 rows x 16 k = 512 float4, 2 per thread
#pragma unroll
        for (int i = 0; i < 2; i++) {
            int idx = tid + i * 256;        // 0..511
            int r   = idx >> 2;             // 0..127
            int kk  = (idx & 3) * 4;
            float4 v = *reinterpret_cast<const float4*>(
                A + (size_t)(bm + r) * K + k0 + kk);
            As[kk + 0][r] = v.x; As[kk + 1][r] = v.y;
            As[kk + 2][r] = v.z; As[kk + 3][r] = v.w;
        }
        // load B tile with N guard
#pragma unroll
        for (int i = 0; i < 2; i++) {
            int idx = tid + i * 256;
            int r   = idx >> 2;
            int kk  = (idx & 3) * 4;
            int n   = bn + r;
            float4 v = make_float4(0.f, 0.f, 0.f, 0.f);
            if (n < N)
                v = *reinterpret_cast<const float4*>(
                    B + (size_t)n * K + k0 + kk);
            Bs[kk + 0][r] = v.x; Bs[kk + 1][r] = v.y;
            Bs[kk + 2][r] = v.z; Bs[kk + 3][r] = v.w;
        }
        __syncthreads();

#pragma unroll
        for (int kk = 0; kk < 16; kk++) {
            float4 a0 = *reinterpret_cast<const float4*>(&As[kk][ty * 4]);
            float4 a1 = *reinterpret_cast<const float4*>(&As[kk][64 + ty * 4]);
            float4 b0 = *reinterpret_cast<const float4*>(&Bs[kk][tx * 4]);
            float4 b1 = *reinterpret_cast<const float4*>(&Bs[kk][64 + tx * 4]);
            float a[8] = {a0.x, a0.y, a0.z, a0.w, a1.x, a1.y, a1.z, a1.w};
            float b[8] = {b0.x, b0.y, b0.z, b0.w, b1.x, b1.y, b1.z, b1.w};
#pragma unroll
            for (int i = 0; i < 8; i++)
#pragma unroll
                for (int j = 0; j < 8; j++)
                    acc[i][j] = fmaf(a[i], b[j], acc[i][j]);
        }
        __syncthreads();
    }

#pragma unroll
    for (int i = 0; i < 8; i++) {
        int m = bm + ((i < 4) ? (ty * 4 + i) : (64 + ty * 4 + i - 4));
#pragma unroll
        for (int j = 0; j < 8; j++) {
            int n = bn + ((j < 4) ? (tx * 4 + j) : (64 + tx * 4 + j - 4));
            if (n < N) C[(size_t)m * N + n] = acc[i][j];
        }
    }
}

// ---------------- depthwise causal conv(4) + silu ---------------------------
__global__ __launch_bounds__(256) void conv_silu_kernel(
    const float* __restrict__ conv_w, const float* __restrict__ conv_b)
{
    int idx = blockIdx.x * 256 + threadIdx.x;     // over ML*D_INNER
    if (idx >= ML * D_INNER) return;
    int c  = idx & (D_INNER - 1);
    int ml = idx >> 11;                            // / 2048
    int l  = ml & (SEQ - 1);
    int b  = ml >> 10;

    float acc = conv_b[c];
#pragma unroll
    for (int k = 0; k < D_CONV; k++) {
        int ls = l + k - (D_CONV - 1);
        if (ls >= 0)
            acc = fmaf(g_zx[(size_t)(b * SEQ + ls) * D_IN_PROJ + D_INNER + c],
                       conv_w[c * D_CONV + k], acc);
    }
    // silu
    acc = acc / (1.f + expf(-acc));
    g_xconv[idx] = acc;
}

// ---------------- a_bar = exp(softplus(Bm + dt_bias) * -exp(A_log)) --------
__global__ __launch_bounds__(256) void abar_kernel(
    const float* __restrict__ A_log, const float* __restrict__ dt_bias)
{
    int idx = blockIdx.x * 256 + threadIdx.x;     // over ML*N_HEADS
    if (idx >= ML * N_HEADS) return;
    int h  = idx & (N_HEADS - 1);
    int ml = idx >> 3;
    float raw = g_zx[(size_t)ml * D_IN_PROJ + 2 * D_INNER + h] + dt_bias[h];
    float sp  = (raw > 20.f) ? raw : log1pf(expf(raw));
    g_abar[idx] = expf(-expf(A_log[h]) * sp);
}

// ---------------- sequential selective scan ---------------------------------
// grid = 32: (b, h, half-of-d). 128 threads = one d each. 64-state in regs.
__global__ __launch_bounds__(128) void scan_kernel(const float* __restrict__ D_param)
{
    const int blk  = blockIdx.x;       // 0..31
    const int half = blk & 1;
    const int h    = (blk >> 1) & 7;
    const int b    = blk >> 4;
    const int d    = half * 128 + threadIdx.x;
    const int c    = h * HEAD_DIM + d;

    float hs[D_STATE];
#pragma unroll
    for (int n = 0; n < D_STATE; n++) hs[n] = 0.f;

    __shared__ float sB[2][D_STATE];
    __shared__ float sC[2][D_STATE];

    const float* zrow = g_zx + (size_t)(b * SEQ) * D_IN_PROJ;

    // preload t = 0 (B at col 4104, C at col 4168)
    {
        const float* p = zrow + 2 * D_INNER + N_HEADS;
        if (threadIdx.x < 64) sB[0][threadIdx.x] = p[threadIdx.x];
        else                  sC[0][threadIdx.x - 64] = p[threadIdx.x];
    }
    __syncthreads();

    const float Dp = D_param[h];
    int buf = 0;
    for (int t = 0; t < SEQ; t++) {
        if (t + 1 < SEQ) {
            const float* p = zrow + (size_t)(t + 1) * D_IN_PROJ + 2 * D_INNER + N_HEADS;
            if (threadIdx.x < 64) sB[buf ^ 1][threadIdx.x] = p[threadIdx.x];
            else                  sC[buf ^ 1][threadIdx.x - 64] = p[threadIdx.x];
        }
        float a = g_abar[(b * SEQ + t) * N_HEADS + h];
        float x = g_xconv[(size_t)(b * SEQ + t) * D_INNER + c];
        float y = 0.f;
#pragma unroll
        for (int n = 0; n < D_STATE; n++) {
            hs[n] = fmaf(a, hs[n], sB[buf][n] * x);
            y     = fmaf(hs[n], sC[buf][n], y);
        }
        float zv = zrow[(size_t)t * D_IN_PROJ + c];
        float gate = zv / (1.f + expf(-zv));
        g_y[(size_t)(b * SEQ + t) * D_INNER + c] = (y + Dp * x) * gate;
        __syncthreads();
        buf ^= 1;
    }
}

// ---------------- rmsnorm (in place on g_y) ---------------------------------
__global__ __launch_bounds__(256) void rmsnorm_kernel(const float* __restrict__ norm_w)
{
    const int row = blockIdx.x;                   // ML rows
    float* y = g_y + (size_t)row * D_INNER;
    float s = 0.f;
    for (int i = threadIdx.x; i < D_INNER; i += 256) {
        float v = y[i];
        s = fmaf(v, v, s);
    }
#pragma unroll
    for (int o = 16; o; o >>= 1) s += __shfl_xor_sync(0xFFFFFFFFu, s, o);
    __shared__ float red[8];
    if ((threadIdx.x & 31) == 0) red[threadIdx.x >> 5] = s;
    __syncthreads();
    if (threadIdx.x < 8) {
        s = red[threadIdx.x];
#pragma unroll
        for (int o = 4; o; o >>= 1) s += __shfl_xor_sync(0xFFu, s, o);
        if (threadIdx.x == 0) red[0] = s;
    }
    __syncthreads();
    const float scale = rsqrtf(red[0] * (1.f / D_INNER) + 1e-6f);
    for (int i = threadIdx.x; i < D_INNER; i += 256)
        y[i] = y[i] * scale * norm_w[i];
}

// ---------------- launch ----------------------------------------------------
extern "C" void kernel_launch(void* const* d_in, const int* in_sizes, int n_in,
                              void* d_out, int out_size)
{
    const float* x          = (const float*)d_in[0];  // [2,1024,1024]
    const float* in_proj_w  = (const float*)d_in[1];  // [4232,1024]
    const float* conv_w     = (const float*)d_in[2];  // [2048,4]
    const float* conv_b     = (const float*)d_in[3];  // [2048]
    const float* A_log      = (const float*)d_in[4];  // [8]
    const float* D_param    = (const float*)d_in[5];  // [8]
    const float* dt_bias    = (const float*)d_in[6];  // [8]
    const float* norm_w     = (const float*)d_in[7];  // [2048]
    const float* out_proj_w = (const float*)d_in[8];  // [1024,2048]
    float* out = (float*)d_out;                        // [2,1024,1024]

    float *p_zx, *p_y;
    cudaGetSymbolAddress((void**)&p_zx, g_zx);
    cudaGetSymbolAddress((void**)&p_y,  g_y);

    // 1. in_proj: g_zx[2048,4232] = x[2048,1024] @ in_proj_w[4232,1024]^T
    {
        dim3 grid((D_IN_PROJ + 127) / 128, ML / 128);
        gemm_nt_kernel<<<grid, 256>>>(x, in_proj_w, p_zx, ML, D_IN_PROJ, DIMM);
    }
    // 2. conv + silu
    conv_silu_kernel<<<(ML * D_INNER) / 256, 256>>>(conv_w, conv_b);
    // 3. a_bar
    abar_kernel<<<(ML * N_HEADS) / 256, 256>>>(A_log, dt_bias);
    // 4. scan (+ D skip + silu(z) gate)
    scan_kernel<<<32, 128>>>(D_param);
    // 5. rmsnorm in place
    rmsnorm_kernel<<<ML, 256>>>(norm_w);
    // 6. out_proj: out[2048,1024] = g_y[2048,2048] @ out_proj_w[1024,2048]^T
    {
        dim3 grid(DIMM / 128, ML / 128);
        gemm_nt_kernel<<<grid, 256>>>(p_y, out_proj_w, out, ML, DIMM, D_INNER);
    }
}

// round 3
// speedup vs baseline: 2.4457x; 2.4457x over previous
#include <cuda_runtime.h>
#include <cuda_bf16.h>
#include <math.h>
#include <stdint.h>

#define BATCH    2
#define SEQ      1024
#define DIMM     1024
#define D_STATE  64
#define D_CONV   4
#define N_HEADS  8
#define D_INNER  2048
#define HEAD_DIM 256
#define D_IN_PROJ 4232          // 2048 + 2048 + 8 + 64 + 64
#define ML       (BATCH*SEQ)    // 2048

// ---------------- scratch (device globals: allocation-free) ----------------
__device__ float g_zx[(size_t)ML * D_IN_PROJ];      // in_proj output
__device__ float g_xconv[(size_t)ML * D_INNER];     // silu(conv(xc)) == xh
__device__ float g_y[(size_t)ML * D_INNER];         // y*silu(z), then normed
__device__ float g_abar[ML * N_HEADS];

// bf16 hi/lo split buffers
__device__ __nv_bfloat16 g_xhi[(size_t)ML * DIMM];
__device__ __nv_bfloat16 g_xlo[(size_t)ML * DIMM];
__device__ __nv_bfloat16 g_w1hi[(size_t)D_IN_PROJ * DIMM];
__device__ __nv_bfloat16 g_w1lo[(size_t)D_IN_PROJ * DIMM];
__device__ __nv_bfloat16 g_yhi[(size_t)ML * D_INNER];
__device__ __nv_bfloat16 g_ylo[(size_t)ML * D_INNER];
__device__ __nv_bfloat16 g_w2hi[(size_t)DIMM * D_INNER];
__device__ __nv_bfloat16 g_w2lo[(size_t)DIMM * D_INNER];

// ---------------- PTX helpers (sm_80-era, compute_103-safe) ----------------
__device__ __forceinline__ uint32_t smem_u32(const void* p) {
    uint32_t a;
    asm("{ .reg .u64 t; cvta.to.shared.u64 t, %1; cvt.u32.u64 %0, t; }"
        : "=r"(a) : "l"(p));
    return a;
}
__device__ __forceinline__ void cp_async16(uint32_t saddr, const void* gaddr, uint32_t srcsz) {
    asm volatile("cp.async.cg.shared.global [%0], [%1], 16, %2;"
                 :: "r"(saddr), "l"(gaddr), "r"(srcsz) : "memory");
}
__device__ __forceinline__ void cp_commit() {
    asm volatile("cp.async.commit_group;" ::: "memory");
}
__device__ __forceinline__ void cp_wait1() {
    asm volatile("cp.async.wait_group 1;" ::: "memory");
}
__device__ __forceinline__ void cp_wait0() {
    asm volatile("cp.async.wait_group 0;" ::: "memory");
}
__device__ __forceinline__ void ldsm_x4(uint32_t* r, uint32_t addr) {
    asm volatile("ldmatrix.sync.aligned.m8n8.x4.shared.b16 {%0,%1,%2,%3}, [%4];"
                 : "=r"(r[0]), "=r"(r[1]), "=r"(r[2]), "=r"(r[3]) : "r"(addr));
}
__device__ __forceinline__ void mma16816(float* c, const uint32_t* a, const uint32_t* b) {
    asm volatile(
        "mma.sync.aligned.m16n8k16.row.col.f32.bf16.bf16.f32 "
        "{%0,%1,%2,%3}, {%4,%5,%6,%7}, {%8,%9}, {%0,%1,%2,%3};"
        : "+f"(c[0]), "+f"(c[1]), "+f"(c[2]), "+f"(c[3])
        : "r"(a[0]), "r"(a[1]), "r"(a[2]), "r"(a[3]), "r"(b[0]), "r"(b[1]));
}

// ---------------- fp32 -> bf16 hi/lo split ----------------------------------
__global__ __launch_bounds__(256) void split_bf16(
    const float* __restrict__ s, __nv_bfloat16* __restrict__ hi,
    __nv_bfloat16* __restrict__ lo, int n4)
{
    int i = blockIdx.x * 256 + threadIdx.x;
    if (i >= n4) return;
    float4 v = reinterpret_cast<const float4*>(s)[i];
    __nv_bfloat16 h0 = __float2bfloat16(v.x);
    __nv_bfloat16 h1 = __float2bfloat16(v.y);
    __nv_bfloat16 h2 = __float2bfloat16(v.z);
    __nv_bfloat16 h3 = __float2bfloat16(v.w);
    __nv_bfloat16 l0 = __float2bfloat16(v.x - __bfloat162float(h0));
    __nv_bfloat16 l1 = __float2bfloat16(v.y - __bfloat162float(h1));
    __nv_bfloat16 l2 = __float2bfloat16(v.z - __bfloat162float(h2));
    __nv_bfloat16 l3 = __float2bfloat16(v.w - __bfloat162float(h3));
    __nv_bfloat162 hh0{h0, h1}, hh1{h2, h3}, ll0{l0, l1}, ll1{l2, l3};
    reinterpret_cast<__nv_bfloat162*>(hi)[i * 2 + 0] = hh0;
    reinterpret_cast<__nv_bfloat162*>(hi)[i * 2 + 1] = hh1;
    reinterpret_cast<__nv_bfloat162*>(lo)[i * 2 + 0] = ll0;
    reinterpret_cast<__nv_bfloat162*>(lo)[i * 2 + 1] = ll1;
}

// ---------------- mma.sync GEMM: C[m,n] = sum_k A[m,k]*B[n,k] (bf16x3) ------
// CTA: 128x128 tile, BK=64, 256 threads = 8 warps (2 along M x 4 along N),
// warp tile 64x32 = 4 m-frags x 4 n-frags of m16n8k16.
// smem per stage: Ah,Al,Bh,Bl each 128x64 bf16 = 16KB -> 64KB; 2 stages = 128KB.
// Swizzle: tile elem (r, j16) -> uint4 index r*8 + (j16 ^ (r&7)).
#define TSZ 16384
__global__ __launch_bounds__(256, 1) void gemm_mma(
    const __nv_bfloat16* __restrict__ Ahi, const __nv_bfloat16* __restrict__ Alo,
    const __nv_bfloat16* __restrict__ Bhi, const __nv_bfloat16* __restrict__ Blo,
    float* __restrict__ C, int M, int N, int K)
{
    extern __shared__ char smem[];
    const int tid  = threadIdx.x;
    const int wid  = tid >> 5;
    const int lane = tid & 31;
    const int bm = blockIdx.y * 128, bn = blockIdx.x * 128;
    const int wm = (wid >> 2) * 64;        // warp M offset (0 or 64)
    const int wn = (wid & 3) * 32;         // warp N offset (0,32,64,96)

    const uint32_t sbase = smem_u32(smem);

    float acc[4][4][4];
#pragma unroll
    for (int mi = 0; mi < 4; mi++)
#pragma unroll
        for (int ni = 0; ni < 4; ni++)
#pragma unroll
            for (int v = 0; v < 4; v++) acc[mi][ni][v] = 0.f;

    // per-thread load coords: 4 chunks per tile per thread
    const int NC = K >> 6;

    auto load_stage = [&](int buf, int k0) {
        uint32_t st = sbase + buf * 4 * TSZ;
#pragma unroll
        for (int it = 0; it < 4; it++) {
            int cid = it * 256 + tid;
            int r = cid >> 3, j = cid & 7;
            uint32_t swz = (uint32_t)((r * 8 + (j ^ (r & 7))) * 16);
            size_t aoff = (size_t)(bm + r) * K + k0 + j * 8;
            cp_async16(st + swz,           Ahi + aoff, 16);
            cp_async16(st + TSZ + swz,     Alo + aoff, 16);
            int n = bn + r;
            uint32_t ok = (n < N) ? 16u : 0u;
            size_t boff = (size_t)(ok ? n : 0) * K + k0 + j * 8;
            cp_async16(st + 2 * TSZ + swz, Bhi + boff, ok);
            cp_async16(st + 3 * TSZ + swz, Blo + boff, ok);
        }
    };

    load_stage(0, 0);
    cp_commit();

    // ldmatrix address components (per thread)
    const int rA = wm + (lane & 15);        // + mi*16
    const int jA = lane >> 4;               // + 2*ks
    const int qB = lane >> 3;
    const int rB = wn + ((qB >= 2) ? 8 : 0) + (lane & 7);  // + npair*16
    const int jB = qB & 1;                  // + 2*ks

    for (int ch = 0; ch < NC; ch++) {
        const int buf = ch & 1;
        if (ch + 1 < NC) { load_stage(buf ^ 1, (ch + 1) << 6); cp_commit(); cp_wait1(); }
        else             { cp_wait0(); }
        __syncthreads();

        uint32_t stA  = sbase + buf * 4 * TSZ;
        uint32_t stAl = stA + TSZ;
        uint32_t stB  = stA + 2 * TSZ;
        uint32_t stBl = stA + 3 * TSZ;

#pragma unroll
        for (int ks = 0; ks < 4; ks++) {
            uint32_t ah[4][4], al[4][4], bh[2][4], bl[2][4];
#pragma unroll
            for (int mi = 0; mi < 4; mi++) {
                int r = rA + mi * 16;
                int jj = 2 * ks + jA;
                uint32_t off = (uint32_t)((r * 8 + (jj ^ (r & 7))) * 16);
                ldsm_x4(ah[mi], stA  + off);
                ldsm_x4(al[mi], stAl + off);
            }
#pragma unroll
            for (int np = 0; np < 2; np++) {
                int r = rB + np * 16;
                int jj = 2 * ks + jB;
                uint32_t off = (uint32_t)((r * 8 + (jj ^ (r & 7))) * 16);
                ldsm_x4(bh[np], stB  + off);
                ldsm_x4(bl[np], stBl + off);
            }
#pragma unroll
            for (int mi = 0; mi < 4; mi++) {
#pragma unroll
                for (int ni = 0; ni < 4; ni++) {
                    const uint32_t* bfh = &bh[ni >> 1][(ni & 1) * 2];
                    const uint32_t* bfl = &bl[ni >> 1][(ni & 1) * 2];
                    mma16816(acc[mi][ni], ah[mi], bfh);   // Ah*Bh
                    mma16816(acc[mi][ni], ah[mi], bfl);   // Ah*Bl
                    mma16816(acc[mi][ni], al[mi], bfh);   // Al*Bh
                }
            }
        }
        __syncthreads();
    }

    // epilogue
    const int gid = lane >> 2, tig = lane & 3;
#pragma unroll
    for (int mi = 0; mi < 4; mi++) {
        int row = bm + wm + mi * 16 + gid;
#pragma unroll
        for (int ni = 0; ni < 4; ni++) {
            int col = bn + wn + ni * 8 + tig * 2;
            if (col < N) {
                float2 lo2 = make_float2(acc[mi][ni][0], acc[mi][ni][1]);
                float2 hi2 = make_float2(acc[mi][ni][2], acc[mi][ni][3]);
                *reinterpret_cast<float2*>(C + (size_t)row * N + col) = lo2;
                *reinterpret_cast<float2*>(C + (size_t)(row + 8) * N + col) = hi2;
            }
        }
    }
}

// ---------------- depthwise causal conv(4) + silu ---------------------------
__global__ __launch_bounds__(256) void conv_silu_kernel(
    const float* __restrict__ conv_w, const float* __restrict__ conv_b)
{
    int idx = blockIdx.x * 256 + threadIdx.x;
    if (idx >= ML * D_INNER) return;
    int c  = idx & (D_INNER - 1);
    int ml = idx >> 11;
    int l  = ml & (SEQ - 1);
    int b  = ml >> 10;

    float acc = conv_b[c];
#pragma unroll
    for (int k = 0; k < D_CONV; k++) {
        int ls = l + k - (D_CONV - 1);
        if (ls >= 0)
            acc = fmaf(g_zx[(size_t)(b * SEQ + ls) * D_IN_PROJ + D_INNER + c],
                       conv_w[c * D_CONV + k], acc);
    }
    acc = acc / (1.f + expf(-acc));
    g_xconv[idx] = acc;
}

// ---------------- a_bar = exp(softplus(Bm + dt_bias) * -exp(A_log)) --------
__global__ __launch_bounds__(256) void abar_kernel(
    const float* __restrict__ A_log, const float* __restrict__ dt_bias)
{
    int idx = blockIdx.x * 256 + threadIdx.x;
    if (idx >= ML * N_HEADS) return;
    int h  = idx & (N_HEADS - 1);
    int ml = idx >> 3;
    float raw = g_zx[(size_t)ml * D_IN_PROJ + 2 * D_INNER + h] + dt_bias[h];
    float sp  = (raw > 20.f) ? raw : log1pf(expf(raw));
    g_abar[idx] = expf(-expf(A_log[h]) * sp);
}

// ---------------- sequential selective scan (128 CTAs) ----------------------
// CTA = (b, h, 32-d block). 128 threads: 4 per d, 16 states each.
__global__ __launch_bounds__(128) void scan_kernel(const float* __restrict__ D_param)
{
    const int b  = blockIdx.x >> 6;
    const int h  = (blockIdx.x >> 3) & 7;
    const int dq = blockIdx.x & 7;
    const int tid = threadIdx.x;
    const int q  = tid & 3;           // state quarter
    const int dl = tid >> 2;          // local d (0..31)
    const int c0 = h * HEAD_DIM + dq * 32;
    const int c  = c0 + dl;

    float hs[16];
#pragma unroll
    for (int n = 0; n < 16; n++) hs[n] = 0.f;

    __shared__ float sBC[2][4][128];
    __shared__ float sx[2][4][32];
    __shared__ float sz[2][4][32];
    __shared__ float sa[2][4];

    const float Dp = D_param[h];
    const size_t rb = (size_t)(b * SEQ);

    auto load_group = [&](int g, int bb) {
        const int t0 = g * 4;
        {   // B|C: 128 contiguous floats per step
            int st = tid >> 5, f4 = tid & 31;
            const float* p = g_zx + (rb + t0 + st) * D_IN_PROJ + 2 * D_INNER + N_HEADS + f4 * 4;
            *reinterpret_cast<float4*>(&sBC[bb][st][f4 * 4]) =
                *reinterpret_cast<const float4*>(p);
        }
        {   // x, z: 32 floats per step
            int st = tid >> 5, ii = tid & 31;
            sx[bb][st][ii] = g_xconv[(rb + t0 + st) * D_INNER + c0 + ii];
            sz[bb][st][ii] = g_zx[(rb + t0 + st) * D_IN_PROJ + c0 + ii];
        }
        if (tid < 4) sa[bb][tid] = g_abar[(rb + t0 + tid) * N_HEADS + h];
    };

    load_group(0, 0);
    __syncthreads();

    for (int g = 0; g < SEQ / 4; g++) {
        const int bb = g & 1;
        if (g + 1 < SEQ / 4) load_group(g + 1, bb ^ 1);
#pragma unroll
        for (int st = 0; st < 4; st++) {
            float a = sa[bb][st];
            float x = sx[bb][st][dl];
            const float4* Bv = reinterpret_cast<const float4*>(&sBC[bb][st][q * 16]);
            const float4* Cv = reinterpret_cast<const float4*>(&sBC[bb][st][64 + q * 16]);
            float y = 0.f;
#pragma unroll
            for (int i = 0; i < 4; i++) {
                float4 bq = Bv[i], cq = Cv[i];
                hs[i*4+0] = fmaf(a, hs[i*4+0], bq.x * x); y = fmaf(hs[i*4+0], cq.x, y);
                hs[i*4+1] = fmaf(a, hs[i*4+1], bq.y * x); y = fmaf(hs[i*4+1], cq.y, y);
                hs[i*4+2] = fmaf(a, hs[i*4+2], bq.z * x); y = fmaf(hs[i*4+2], cq.z, y);
                hs[i*4+3] = fmaf(a, hs[i*4+3], bq.w * x); y = fmaf(hs[i*4+3], cq.w, y);
            }
            y += __shfl_xor_sync(0xFFFFFFFFu, y, 1);
            y += __shfl_xor_sync(0xFFFFFFFFu, y, 2);
            if (q == 0) {
                float zv = sz[bb][st][dl];
                float gate = zv / (1.f + expf(-zv));
                g_y[(rb + g * 4 + st) * D_INNER + c] = (y + Dp * x) * gate;
            }
        }
        __syncthreads();
    }
}

// ---------------- rmsnorm (in place on g_y) ---------------------------------
__global__ __launch_bounds__(256) void rmsnorm_kernel(const float* __restrict__ norm_w)
{
    const int row = blockIdx.x;
    float* y = g_y + (size_t)row * D_INNER;
    float s = 0.f;
    for (int i = threadIdx.x; i < D_INNER; i += 256) {
        float v = y[i];
        s = fmaf(v, v, s);
    }
#pragma unroll
    for (int o = 16; o; o >>= 1) s += __shfl_xor_sync(0xFFFFFFFFu, s, o);
    __shared__ float red[8];
    if ((threadIdx.x & 31) == 0) red[threadIdx.x >> 5] = s;
    __syncthreads();
    if (threadIdx.x < 8) {
        s = red[threadIdx.x];
#pragma unroll
        for (int o = 4; o; o >>= 1) s += __shfl_xor_sync(0xFFu, s, o);
        if (threadIdx.x == 0) red[0] = s;
    }
    __syncthreads();
    const float scale = rsqrtf(red[0] * (1.f / D_INNER) + 1e-6f);
    for (int i = threadIdx.x; i < D_INNER; i += 256)
        y[i] = y[i] * scale * norm_w[i];
}

// ---------------- launch ----------------------------------------------------
extern "C" void kernel_launch(void* const* d_in, const int* in_sizes, int n_in,
                              void* d_out, int out_size)
{
    const float* x          = (const float*)d_in[0];
    const float* in_proj_w  = (const float*)d_in[1];
    const float* conv_w     = (const float*)d_in[2];
    const float* conv_b     = (const float*)d_in[3];
    const float* A_log      = (const float*)d_in[4];
    const float* D_param    = (const float*)d_in[5];
    const float* dt_bias    = (const float*)d_in[6];
    const float* norm_w     = (const float*)d_in[7];
    const float* out_proj_w = (const float*)d_in[8];
    float* out = (float*)d_out;

    float *p_zx, *p_y;
    __nv_bfloat16 *p_xhi, *p_xlo, *p_w1hi, *p_w1lo, *p_yhi, *p_ylo, *p_w2hi, *p_w2lo;
    cudaGetSymbolAddress((void**)&p_zx,   g_zx);
    cudaGetSymbolAddress((void**)&p_y,    g_y);
    cudaGetSymbolAddress((void**)&p_xhi,  g_xhi);
    cudaGetSymbolAddress((void**)&p_xlo,  g_xlo);
    cudaGetSymbolAddress((void**)&p_w1hi, g_w1hi);
    cudaGetSymbolAddress((void**)&p_w1lo, g_w1lo);
    cudaGetSymbolAddress((void**)&p_yhi,  g_yhi);
    cudaGetSymbolAddress((void**)&p_ylo,  g_ylo);
    cudaGetSymbolAddress((void**)&p_w2hi, g_w2hi);
    cudaGetSymbolAddress((void**)&p_w2lo, g_w2lo);

    const int dyn_smem = 8 * TSZ;   // 128KB
    cudaFuncSetAttribute(gemm_mma, cudaFuncAttributeMaxDynamicSharedMemorySize, dyn_smem);

    // 0. split inputs to bf16 hi/lo
    {
        int n4x = (ML * DIMM) / 4;
        split_bf16<<<(n4x + 255) / 256, 256>>>(x, p_xhi, p_xlo, n4x);
        int n4w = (D_IN_PROJ * DIMM) / 4;
        split_bf16<<<(n4w + 255) / 256, 256>>>(in_proj_w, p_w1hi, p_w1lo, n4w);
        int n4w2 = (DIMM * D_INNER) / 4;
        split_bf16<<<(n4w2 + 255) / 256, 256>>>(out_proj_w, p_w2hi, p_w2lo, n4w2);
    }
    // 1. in_proj: g_zx[2048,4232]
    {
        dim3 grid((D_IN_PROJ + 127) / 128, ML / 128);
        gemm_mma<<<grid, 256, dyn_smem>>>(p_xhi, p_xlo, p_w1hi, p_w1lo,
                                          p_zx, ML, D_IN_PROJ, DIMM);
    }
    // 2. conv + silu
    conv_silu_kernel<<<(ML * D_INNER) / 256, 256>>>(conv_w, conv_b);
    // 3. a_bar
    abar_kernel<<<(ML * N_HEADS) / 256, 256>>>(A_log, dt_bias);
    // 4. scan
    scan_kernel<<<128, 128>>>(D_param);
    // 5. rmsnorm in place
    rmsnorm_kernel<<<ML, 256>>>(norm_w);
    // 6. split y to bf16 hi/lo
    {
        int n4y = (ML * D_INNER) / 4;
        split_bf16<<<(n4y + 255) / 256, 256>>>(p_y, p_yhi, p_ylo, n4y);
    }
    // 7. out_proj: out[2048,1024]
    {
        dim3 grid(DIMM / 128, ML / 128);
        gemm_mma<<<grid, 256, dyn_smem>>>(p_yhi, p_ylo, p_w2hi, p_w2lo,
                                          out, ML, DIMM, D_INNER);
    }
}

// round 5
// speedup vs baseline: 3.4950x; 1.4290x over previous
#include <cuda_runtime.h>
#include <cuda_bf16.h>
#include <math.h>
#include <stdint.h>

#define BATCH    2
#define SEQ      1024
#define DIMM     1024
#define D_STATE  64
#define D_CONV   4
#define N_HEADS  8
#define D_INNER  2048
#define HEAD_DIM 256
#define D_IN_PROJ 4232          // 2048 + 2048 + 8 + 64 + 64
#define ML       (BATCH*SEQ)    // 2048
#define NSEG     8
#define SEG_LEN  128            // SEQ / NSEG

// ---------------- scratch (device globals: allocation-free) ----------------
__device__ float g_zx[(size_t)ML * D_IN_PROJ];      // in_proj output
__device__ float g_xconv[(size_t)ML * D_INNER];     // silu(conv(xc)) == xh
__device__ float g_y[(size_t)ML * D_INNER];         // (y+Dx)*silu(z)
__device__ float g_abar[ML * N_HEADS];
__device__ float g_aseg[BATCH * N_HEADS * NSEG];    // per-segment decay product
__device__ float g_state[(size_t)BATCH * N_HEADS * NSEG * HEAD_DIM * D_STATE]; // 8MB
__device__ float g_hinit[(size_t)BATCH * N_HEADS * NSEG * HEAD_DIM * D_STATE]; // 8MB

// bf16 hi/lo split buffers
__device__ __nv_bfloat16 g_xhi[(size_t)ML * DIMM];
__device__ __nv_bfloat16 g_xlo[(size_t)ML * DIMM];
__device__ __nv_bfloat16 g_w1hi[(size_t)D_IN_PROJ * DIMM];
__device__ __nv_bfloat16 g_w1lo[(size_t)D_IN_PROJ * DIMM];
__device__ __nv_bfloat16 g_yhi[(size_t)ML * D_INNER];
__device__ __nv_bfloat16 g_ylo[(size_t)ML * D_INNER];
__device__ __nv_bfloat16 g_w2hi[(size_t)DIMM * D_INNER];
__device__ __nv_bfloat16 g_w2lo[(size_t)DIMM * D_INNER];

// ---------------- PTX helpers (sm_80-era, compute_103-safe) ----------------
__device__ __forceinline__ uint32_t smem_u32(const void* p) {
    uint32_t a;
    asm("{ .reg .u64 t; cvta.to.shared.u64 t, %1; cvt.u32.u64 %0, t; }"
        : "=r"(a) : "l"(p));
    return a;
}
__device__ __forceinline__ void cp_async16(uint32_t saddr, const void* gaddr, uint32_t srcsz) {
    asm volatile("cp.async.cg.shared.global [%0], [%1], 16, %2;"
                 :: "r"(saddr), "l"(gaddr), "r"(srcsz) : "memory");
}
__device__ __forceinline__ void cp_commit() {
    asm volatile("cp.async.commit_group;" ::: "memory");
}
__device__ __forceinline__ void cp_wait2() {
    asm volatile("cp.async.wait_group 2;" ::: "memory");
}
__device__ __forceinline__ void ldsm_x4(uint32_t* r, uint32_t addr) {
    asm volatile("ldmatrix.sync.aligned.m8n8.x4.shared.b16 {%0,%1,%2,%3}, [%4];"
                 : "=r"(r[0]), "=r"(r[1]), "=r"(r[2]), "=r"(r[3]) : "r"(addr));
}
__device__ __forceinline__ void mma16816(float* c, const uint32_t* a, const uint32_t* b) {
    asm volatile(
        "mma.sync.aligned.m16n8k16.row.col.f32.bf16.bf16.f32 "
        "{%0,%1,%2,%3}, {%4,%5,%6,%7}, {%8,%9}, {%0,%1,%2,%3};"
        : "+f"(c[0]), "+f"(c[1]), "+f"(c[2]), "+f"(c[3])
        : "r"(a[0]), "r"(a[1]), "r"(a[2]), "r"(a[3]), "r"(b[0]), "r"(b[1]));
}

// ---------------- fp32 -> bf16 hi/lo split ----------------------------------
__global__ __launch_bounds__(256) void split_bf16(
    const float* __restrict__ s, __nv_bfloat16* __restrict__ hi,
    __nv_bfloat16* __restrict__ lo, int n4)
{
    int i = blockIdx.x * 256 + threadIdx.x;
    if (i >= n4) return;
    float4 v = reinterpret_cast<const float4*>(s)[i];
    __nv_bfloat16 h0 = __float2bfloat16(v.x);
    __nv_bfloat16 h1 = __float2bfloat16(v.y);
    __nv_bfloat16 h2 = __float2bfloat16(v.z);
    __nv_bfloat16 h3 = __float2bfloat16(v.w);
    __nv_bfloat16 l0 = __float2bfloat16(v.x - __bfloat162float(h0));
    __nv_bfloat16 l1 = __float2bfloat16(v.y - __bfloat162float(h1));
    __nv_bfloat16 l2 = __float2bfloat16(v.z - __bfloat162float(h2));
    __nv_bfloat16 l3 = __float2bfloat16(v.w - __bfloat162float(h3));
    __nv_bfloat162 hh0{h0, h1}, hh1{h2, h3}, ll0{l0, l1}, ll1{l2, l3};
    reinterpret_cast<__nv_bfloat162*>(hi)[i * 2 + 0] = hh0;
    reinterpret_cast<__nv_bfloat162*>(hi)[i * 2 + 1] = hh1;
    reinterpret_cast<__nv_bfloat162*>(lo)[i * 2 + 0] = ll0;
    reinterpret_cast<__nv_bfloat162*>(lo)[i * 2 + 1] = ll1;
}

// ---------------- mma.sync GEMM (bf16x3, 3-stage cp.async pipeline) ---------
// CTA: 128x128 tile, BK=64, 256 threads = 8 warps (2M x 4N), warp tile 64x32.
// smem per stage: Ah,Al,Bh,Bl each 128x64 bf16 = 16KB -> 64KB; 3 stages = 192KB.
#define TSZ 16384
__global__ __launch_bounds__(256, 1) void gemm_mma(
    const __nv_bfloat16* __restrict__ Ahi, const __nv_bfloat16* __restrict__ Alo,
    const __nv_bfloat16* __restrict__ Bhi, const __nv_bfloat16* __restrict__ Blo,
    float* __restrict__ C, int M, int N, int K)
{
    extern __shared__ char smem[];
    const int tid  = threadIdx.x;
    const int wid  = tid >> 5;
    const int lane = tid & 31;
    const int bm = blockIdx.y * 128, bn = blockIdx.x * 128;
    const int wm = (wid >> 2) * 64;
    const int wn = (wid & 3) * 32;

    const uint32_t sbase = smem_u32(smem);

    float acc[4][4][4];
#pragma unroll
    for (int mi = 0; mi < 4; mi++)
#pragma unroll
        for (int ni = 0; ni < 4; ni++)
#pragma unroll
            for (int v = 0; v < 4; v++) acc[mi][ni][v] = 0.f;

    const int NC = K >> 6;

    auto load_stage = [&](int buf, int k0) {
        uint32_t st = sbase + buf * 4 * TSZ;
#pragma unroll
        for (int it = 0; it < 4; it++) {
            int cid = it * 256 + tid;
            int r = cid >> 3, j = cid & 7;
            uint32_t swz = (uint32_t)((r * 8 + (j ^ (r & 7))) * 16);
            size_t aoff = (size_t)(bm + r) * K + k0 + j * 8;
            cp_async16(st + swz,           Ahi + aoff, 16);
            cp_async16(st + TSZ + swz,     Alo + aoff, 16);
            int n = bn + r;
            uint32_t ok = (n < N) ? 16u : 0u;
            size_t boff = (size_t)(ok ? n : 0) * K + k0 + j * 8;
            cp_async16(st + 2 * TSZ + swz, Bhi + boff, ok);
            cp_async16(st + 3 * TSZ + swz, Blo + boff, ok);
        }
    };

    load_stage(0, 0);  cp_commit();
    load_stage(1, 64); cp_commit();

    const int rA = wm + (lane & 15);
    const int jA = lane >> 4;
    const int qB = lane >> 3;
    const int rB = wn + ((qB >= 2) ? 8 : 0) + (lane & 7);
    const int jB = qB & 1;

    int buf = 0;
    for (int ch = 0; ch < NC; ch++) {
        if (ch + 2 < NC) load_stage((buf + 2 >= 3) ? buf - 1 : buf + 2, (ch + 2) << 6);
        cp_commit();
        cp_wait2();
        __syncthreads();

        uint32_t stA  = sbase + buf * 4 * TSZ;
        uint32_t stAl = stA + TSZ;
        uint32_t stB  = stA + 2 * TSZ;
        uint32_t stBl = stA + 3 * TSZ;

#pragma unroll
        for (int ks = 0; ks < 4; ks++) {
            uint32_t ah[4][4], al[4][4], bh[2][4], bl[2][4];
#pragma unroll
            for (int mi = 0; mi < 4; mi++) {
                int r = rA + mi * 16;
                int jj = 2 * ks + jA;
                uint32_t off = (uint32_t)((r * 8 + (jj ^ (r & 7))) * 16);
                ldsm_x4(ah[mi], stA  + off);
                ldsm_x4(al[mi], stAl + off);
            }
#pragma unroll
            for (int np = 0; np < 2; np++) {
                int r = rB + np * 16;
                int jj = 2 * ks + jB;
                uint32_t off = (uint32_t)((r * 8 + (jj ^ (r & 7))) * 16);
                ldsm_x4(bh[np], stB  + off);
                ldsm_x4(bl[np], stBl + off);
            }
#pragma unroll
            for (int mi = 0; mi < 4; mi++) {
#pragma unroll
                for (int ni = 0; ni < 4; ni++) {
                    const uint32_t* bfh = &bh[ni >> 1][(ni & 1) * 2];
                    const uint32_t* bfl = &bl[ni >> 1][(ni & 1) * 2];
                    mma16816(acc[mi][ni], ah[mi], bfh);
                    mma16816(acc[mi][ni], ah[mi], bfl);
                    mma16816(acc[mi][ni], al[mi], bfh);
                }
            }
        }
        __syncthreads();
        buf = (buf + 1 >= 3) ? 0 : buf + 1;
    }

    const int gid = lane >> 2, tig = lane & 3;
#pragma unroll
    for (int mi = 0; mi < 4; mi++) {
        int row = bm + wm + mi * 16 + gid;
#pragma unroll
        for (int ni = 0; ni < 4; ni++) {
            int col = bn + wn + ni * 8 + tig * 2;
            if (col < N) {
                float2 lo2 = make_float2(acc[mi][ni][0], acc[mi][ni][1]);
                float2 hi2 = make_float2(acc[mi][ni][2], acc[mi][ni][3]);
                *reinterpret_cast<float2*>(C + (size_t)row * N + col) = lo2;
                *reinterpret_cast<float2*>(C + (size_t)(row + 8) * N + col) = hi2;
            }
        }
    }
}

// ---------------- depthwise causal conv(4) + silu ---------------------------
__global__ __launch_bounds__(256) void conv_silu_kernel(
    const float* __restrict__ conv_w, const float* __restrict__ conv_b)
{
    int idx = blockIdx.x * 256 + threadIdx.x;
    if (idx >= ML * D_INNER) return;
    int c  = idx & (D_INNER - 1);
    int ml = idx >> 11;
    int l  = ml & (SEQ - 1);
    int b  = ml >> 10;

    float acc = conv_b[c];
#pragma unroll
    for (int k = 0; k < D_CONV; k++) {
        int ls = l + k - (D_CONV - 1);
        if (ls >= 0)
            acc = fmaf(g_zx[(size_t)(b * SEQ + ls) * D_IN_PROJ + D_INNER + c],
                       conv_w[c * D_CONV + k], acc);
    }
    acc = acc / (1.f + expf(-acc));
    g_xconv[idx] = acc;
}

// ---------------- a_bar = exp(softplus(Bm + dt_bias) * -exp(A_log)) --------
__global__ __launch_bounds__(256) void abar_kernel(
    const float* __restrict__ A_log, const float* __restrict__ dt_bias)
{
    int idx = blockIdx.x * 256 + threadIdx.x;
    if (idx >= ML * N_HEADS) return;
    int h  = idx & (N_HEADS - 1);
    int ml = idx >> 3;
    float raw = g_zx[(size_t)ml * D_IN_PROJ + 2 * D_INNER + h] + dt_bias[h];
    float sp  = (raw > 20.f) ? raw : log1pf(expf(raw));
    g_abar[idx] = expf(-expf(A_log[h]) * sp);
}

// ---------------- per-segment decay products --------------------------------
__global__ __launch_bounds__(128) void aseg_kernel()
{
    int tid = threadIdx.x;             // = (b*8+h)*8 + seg
    int seg = tid & 7;
    int h   = (tid >> 3) & 7;
    int b   = tid >> 6;
    float p = 1.f;
    int t0 = seg * SEG_LEN;
#pragma unroll 8
    for (int t = 0; t < SEG_LEN; t++)
        p *= g_abar[(b * SEQ + t0 + t) * N_HEADS + h];
    g_aseg[tid] = p;
}

// ---------------- scan pass A: per-segment local state (zero init) ----------
// grid 1024: (b,h,seg,dq). 128 threads: 4/d (q=state quarter), 32 d per CTA.
__global__ __launch_bounds__(128) void scan_partA()
{
    const int bx = blockIdx.x;
    const int dq = bx & 7, seg = (bx >> 3) & 7, h = (bx >> 6) & 7, b = bx >> 9;
    const int tid = threadIdx.x;
    const int q  = tid & 3;
    const int dl = tid >> 2;
    const int c0 = h * HEAD_DIM + dq * 32;

    float hs[16];
#pragma unroll
    for (int n = 0; n < 16; n++) hs[n] = 0.f;

    __shared__ float sB[2][4][64];
    __shared__ float sx[2][4][32];
    __shared__ float sa[2][4];

    const size_t rb = (size_t)b * SEQ + seg * SEG_LEN;

    auto load_group = [&](int g, int bb) {
        const int t0 = g * 4;
        if (tid < 64) {
            int st = tid >> 4, f = tid & 15;
            const float* p = g_zx + (rb + t0 + st) * D_IN_PROJ + 2 * D_INNER + N_HEADS + f * 4;
            *reinterpret_cast<float4*>(&sB[bb][st][f * 4]) = *reinterpret_cast<const float4*>(p);
        }
        { int st = tid >> 5, ii = tid & 31;
          sx[bb][st][ii] = g_xconv[(rb + t0 + st) * D_INNER + c0 + ii]; }
        if (tid < 4) sa[bb][tid] = g_abar[(rb + t0 + tid) * N_HEADS + h];
    };

    load_group(0, 0);
    __syncthreads();

    for (int g = 0; g < SEG_LEN / 4; g++) {
        const int bb = g & 1;
        if (g + 1 < SEG_LEN / 4) load_group(g + 1, bb ^ 1);
#pragma unroll
        for (int st = 0; st < 4; st++) {
            float a = sa[bb][st];
            float x = sx[bb][st][dl];
            const float4* Bv = reinterpret_cast<const float4*>(&sB[bb][st][q * 16]);
#pragma unroll
            for (int i = 0; i < 4; i++) {
                float4 bq = Bv[i];
                hs[i*4+0] = fmaf(a, hs[i*4+0], bq.x * x);
                hs[i*4+1] = fmaf(a, hs[i*4+1], bq.y * x);
                hs[i*4+2] = fmaf(a, hs[i*4+2], bq.z * x);
                hs[i*4+3] = fmaf(a, hs[i*4+3], bq.w * x);
            }
        }
        __syncthreads();
    }

    size_t base = (((size_t)(b * 8 + h) * 8 + seg) * (HEAD_DIM * D_STATE))
                + (size_t)(dq * 32 + dl) * 64 + q * 16;
#pragma unroll
    for (int i = 0; i < 4; i++)
        *reinterpret_cast<float4*>(&g_state[base + i * 4]) =
            make_float4(hs[i*4+0], hs[i*4+1], hs[i*4+2], hs[i*4+3]);
}

// ---------------- scan pass B: combine segment summaries --------------------
// one thread per (b,h,d,n) = 262144
__global__ __launch_bounds__(256) void combine_kernel()
{
    int idx = blockIdx.x * 256 + threadIdx.x;
    if (idx >= BATCH * N_HEADS * HEAD_DIM * D_STATE) return;
    int bh = idx >> 14;
    int dn = idx & 16383;
    const size_t SS = HEAD_DIM * D_STATE;
    float H = 0.f;
    g_hinit[((size_t)bh * 8) * SS + dn] = 0.f;
#pragma unroll
    for (int seg = 1; seg < NSEG; seg++) {
        float A = g_aseg[bh * 8 + seg - 1];
        H = fmaf(A, H, g_state[((size_t)bh * 8 + seg - 1) * SS + dn]);
        g_hinit[((size_t)bh * 8 + seg) * SS + dn] = H;
    }
}

// ---------------- scan pass C: local scan with carried init + y + gate ------
__global__ __launch_bounds__(128) void scan_partC(const float* __restrict__ D_param)
{
    const int bx = blockIdx.x;
    const int dq = bx & 7, seg = (bx >> 3) & 7, h = (bx >> 6) & 7, b = bx >> 9;
    const int tid = threadIdx.x;
    const int q  = tid & 3;
    const int dl = tid >> 2;
    const int c0 = h * HEAD_DIM + dq * 32;
    const int c  = c0 + dl;

    float hs[16];
    {
        size_t base = (((size_t)(b * 8 + h) * 8 + seg) * (HEAD_DIM * D_STATE))
                    + (size_t)(dq * 32 + dl) * 64 + q * 16;
#pragma unroll
        for (int i = 0; i < 4; i++) {
            float4 v = *reinterpret_cast<const float4*>(&g_hinit[base + i * 4]);
            hs[i*4+0] = v.x; hs[i*4+1] = v.y; hs[i*4+2] = v.z; hs[i*4+3] = v.w;
        }
    }

    __shared__ float sBC[2][4][128];
    __shared__ float sx[2][4][32];
    __shared__ float sz[2][4][32];
    __shared__ float sa[2][4];

    const float Dp = D_param[h];
    const size_t rb = (size_t)b * SEQ + seg * SEG_LEN;

    auto load_group = [&](int g, int bb) {
        const int t0 = g * 4;
        {   int st = tid >> 5, f4 = tid & 31;
            const float* p = g_zx + (rb + t0 + st) * D_IN_PROJ + 2 * D_INNER + N_HEADS + f4 * 4;
            *reinterpret_cast<float4*>(&sBC[bb][st][f4 * 4]) = *reinterpret_cast<const float4*>(p); }
        {   int st = tid >> 5, ii = tid & 31;
            sx[bb][st][ii] = g_xconv[(rb + t0 + st) * D_INNER + c0 + ii];
            sz[bb][st][ii] = g_zx[(rb + t0 + st) * D_IN_PROJ + c0 + ii]; }
        if (tid < 4) sa[bb][tid] = g_abar[(rb + t0 + tid) * N_HEADS + h];
    };

    load_group(0, 0);
    __syncthreads();

    for (int g = 0; g < SEG_LEN / 4; g++) {
        const int bb = g & 1;
        if (g + 1 < SEG_LEN / 4) load_group(g + 1, bb ^ 1);
#pragma unroll
        for (int st = 0; st < 4; st++) {
            float a = sa[bb][st];
            float x = sx[bb][st][dl];
            const float4* Bv = reinterpret_cast<const float4*>(&sBC[bb][st][q * 16]);
            const float4* Cv = reinterpret_cast<const float4*>(&sBC[bb][st][64 + q * 16]);
            float y = 0.f;
#pragma unroll
            for (int i = 0; i < 4; i++) {
                float4 bq = Bv[i], cq = Cv[i];
                hs[i*4+0] = fmaf(a, hs[i*4+0], bq.x * x); y = fmaf(hs[i*4+0], cq.x, y);
                hs[i*4+1] = fmaf(a, hs[i*4+1], bq.y * x); y = fmaf(hs[i*4+1], cq.y, y);
                hs[i*4+2] = fmaf(a, hs[i*4+2], bq.z * x); y = fmaf(hs[i*4+2], cq.z, y);
                hs[i*4+3] = fmaf(a, hs[i*4+3], bq.w * x); y = fmaf(hs[i*4+3], cq.w, y);
            }
            y += __shfl_xor_sync(0xFFFFFFFFu, y, 1);
            y += __shfl_xor_sync(0xFFFFFFFFu, y, 2);
            if (q == 0) {
                float zv = sz[bb][st][dl];
                float gate = zv / (1.f + expf(-zv));
                g_y[(rb + g * 4 + st) * D_INNER + c] = (y + Dp * x) * gate;
            }
        }
        __syncthreads();
    }
}

// ---------------- rmsnorm + bf16 hi/lo split fused ---------------------------
__global__ __launch_bounds__(256) void rmsnorm_split_kernel(const float* __restrict__ norm_w)
{
    const int row = blockIdx.x;
    const float* y = g_y + (size_t)row * D_INNER;
    float4 v[2];
    float s = 0.f;
#pragma unroll
    for (int it = 0; it < 2; it++) {
        v[it] = reinterpret_cast<const float4*>(y)[threadIdx.x + it * 256];
        s = fmaf(v[it].x, v[it].x, s);
        s = fmaf(v[it].y, v[it].y, s);
        s = fmaf(v[it].z, v[it].z, s);
        s = fmaf(v[it].w, v[it].w, s);
    }
#pragma unroll
    for (int o = 16; o; o >>= 1) s += __shfl_xor_sync(0xFFFFFFFFu, s, o);
    __shared__ float red[8];
    if ((threadIdx.x & 31) == 0) red[threadIdx.x >> 5] = s;
    __syncthreads();
    if (threadIdx.x < 8) {
        s = red[threadIdx.x];
#pragma unroll
        for (int o = 4; o; o >>= 1) s += __shfl_xor_sync(0xFFu, s, o);
        if (threadIdx.x == 0) red[0] = s;
    }
    __syncthreads();
    const float scale = rsqrtf(red[0] * (1.f / D_INNER) + 1e-6f);

    __nv_bfloat16* hi = g_yhi + (size_t)row * D_INNER;
    __nv_bfloat16* lo = g_ylo + (size_t)row * D_INNER;
#pragma unroll
    for (int it = 0; it < 2; it++) {
        int i4 = threadIdx.x + it * 256;
        float4 w = reinterpret_cast<const float4*>(norm_w)[i4];
        float f0 = v[it].x * scale * w.x;
        float f1 = v[it].y * scale * w.y;
        float f2 = v[it].z * scale * w.z;
        float f3 = v[it].w * scale * w.w;
        __nv_bfloat16 h0 = __float2bfloat16(f0);
        __nv_bfloat16 h1 = __float2bfloat16(f1);
        __nv_bfloat16 h2 = __float2bfloat16(f2);
        __nv_bfloat16 h3 = __float2bfloat16(f3);
        __nv_bfloat16 l0 = __float2bfloat16(f0 - __bfloat162float(h0));
        __nv_bfloat16 l1 = __float2bfloat16(f1 - __bfloat162float(h1));
        __nv_bfloat16 l2 = __float2bfloat16(f2 - __bfloat162float(h2));
        __nv_bfloat16 l3 = __float2bfloat16(f3 - __bfloat162float(h3));
        __nv_bfloat162 hh0{h0, h1}, hh1{h2, h3}, ll0{l0, l1}, ll1{l2, l3};
        reinterpret_cast<__nv_bfloat162*>(hi)[i4 * 2 + 0] = hh0;
        reinterpret_cast<__nv_bfloat162*>(hi)[i4 * 2 + 1] = hh1;
        reinterpret_cast<__nv_bfloat162*>(lo)[i4 * 2 + 0] = ll0;
        reinterpret_cast<__nv_bfloat162*>(lo)[i4 * 2 + 1] = ll1;
    }
}

// ---------------- launch ----------------------------------------------------
extern "C" void kernel_launch(void* const* d_in, const int* in_sizes, int n_in,
                              void* d_out, int out_size)
{
    const float* x          = (const float*)d_in[0];
    const float* in_proj_w  = (const float*)d_in[1];
    const float* conv_w     = (const float*)d_in[2];
    const float* conv_b     = (const float*)d_in[3];
    const float* A_log      = (const float*)d_in[4];
    const float* D_param    = (const float*)d_in[5];
    const float* dt_bias    = (const float*)d_in[6];
    const float* norm_w     = (const float*)d_in[7];
    const float* out_proj_w = (const float*)d_in[8];
    float* out = (float*)d_out;

    float *p_zx;
    __nv_bfloat16 *p_xhi, *p_xlo, *p_w1hi, *p_w1lo, *p_yhi, *p_ylo, *p_w2hi, *p_w2lo;
    cudaGetSymbolAddress((void**)&p_zx,   g_zx);
    cudaGetSymbolAddress((void**)&p_xhi,  g_xhi);
    cudaGetSymbolAddress((void**)&p_xlo,  g_xlo);
    cudaGetSymbolAddress((void**)&p_w1hi, g_w1hi);
    cudaGetSymbolAddress((void**)&p_w1lo, g_w1lo);
    cudaGetSymbolAddress((void**)&p_yhi,  g_yhi);
    cudaGetSymbolAddress((void**)&p_ylo,  g_ylo);
    cudaGetSymbolAddress((void**)&p_w2hi, g_w2hi);
    cudaGetSymbolAddress((void**)&p_w2lo, g_w2lo);

    const int dyn_smem = 12 * TSZ;   // 192KB (3 stages)
    cudaFuncSetAttribute(gemm_mma, cudaFuncAttributeMaxDynamicSharedMemorySize, dyn_smem);

    // 0. split inputs to bf16 hi/lo
    {
        int n4x = (ML * DIMM) / 4;
        split_bf16<<<(n4x + 255) / 256, 256>>>(x, p_xhi, p_xlo, n4x);
        int n4w = (D_IN_PROJ * DIMM) / 4;
        split_bf16<<<(n4w + 255) / 256, 256>>>(in_proj_w, p_w1hi, p_w1lo, n4w);
        int n4w2 = (DIMM * D_INNER) / 4;
        split_bf16<<<(n4w2 + 255) / 256, 256>>>(out_proj_w, p_w2hi, p_w2lo, n4w2);
    }
    // 1. in_proj
    {
        dim3 grid((D_IN_PROJ + 127) / 128, ML / 128);
        gemm_mma<<<grid, 256, dyn_smem>>>(p_xhi, p_xlo, p_w1hi, p_w1lo,
                                          p_zx, ML, D_IN_PROJ, DIMM);
    }
    // 2. conv + silu
    conv_silu_kernel<<<(ML * D_INNER) / 256, 256>>>(conv_w, conv_b);
    // 3. a_bar + segment products
    abar_kernel<<<(ML * N_HEADS) / 256, 256>>>(A_log, dt_bias);
    aseg_kernel<<<1, 128>>>();
    // 4. two-level scan
    scan_partA<<<1024, 128>>>();
    combine_kernel<<<(BATCH * N_HEADS * HEAD_DIM * D_STATE) / 256, 256>>>();
    scan_partC<<<1024, 128>>>(D_param);
    // 5. rmsnorm + y split fused
    rmsnorm_split_kernel<<<ML, 256>>>(norm_w);
    // 6. out_proj
    {
        dim3 grid(DIMM / 128, ML / 128);
        gemm_mma<<<grid, 256, dyn_smem>>>(p_yhi, p_ylo, p_w2hi, p_w2lo,
                                          out, ML, DIMM, D_INNER);
    }
}

// round 6
// speedup vs baseline: 3.5476x; 1.0151x over previous
#include <cuda_runtime.h>
#include <cuda_bf16.h>
#include <math.h>
#include <stdint.h>

#define BATCH    2
#define SEQ      1024
#define DIMM     1024
#define D_STATE  64
#define D_CONV   4
#define N_HEADS  8
#define D_INNER  2048
#define HEAD_DIM 256
#define D_IN_PROJ 4232          // 2048 + 2048 + 8 + 64 + 64
#define ML       (BATCH*SEQ)    // 2048
#define NSEG     8
#define SEG_LEN  128            // SEQ / NSEG

// ---------------- scratch (device globals: allocation-free) ----------------
__device__ float g_zx[(size_t)ML * D_IN_PROJ];      // in_proj output
__device__ float g_xconv[(size_t)ML * D_INNER];     // silu(conv(xc)) == xh
__device__ float g_y[(size_t)ML * D_INNER];         // (y+Dx)*silu(z)
__device__ float g_abar[ML * N_HEADS];
__device__ float g_aseg[BATCH * N_HEADS * NSEG];    // per-segment decay product
__device__ float g_state[(size_t)BATCH * N_HEADS * NSEG * HEAD_DIM * D_STATE]; // 8MB

// bf16 hi/lo split buffers
__device__ __nv_bfloat16 g_xhi[(size_t)ML * DIMM];
__device__ __nv_bfloat16 g_xlo[(size_t)ML * DIMM];
__device__ __nv_bfloat16 g_w1hi[(size_t)D_IN_PROJ * DIMM];
__device__ __nv_bfloat16 g_w1lo[(size_t)D_IN_PROJ * DIMM];
__device__ __nv_bfloat16 g_yhi[(size_t)ML * D_INNER];
__device__ __nv_bfloat16 g_ylo[(size_t)ML * D_INNER];
__device__ __nv_bfloat16 g_w2hi[(size_t)DIMM * D_INNER];
__device__ __nv_bfloat16 g_w2lo[(size_t)DIMM * D_INNER];

// ---------------- PTX helpers (sm_80-era, compute_103-safe) ----------------
__device__ __forceinline__ uint32_t smem_u32(const void* p) {
    uint32_t a;
    asm("{ .reg .u64 t; cvta.to.shared.u64 t, %1; cvt.u32.u64 %0, t; }"
        : "=r"(a) : "l"(p));
    return a;
}
__device__ __forceinline__ void cp_async16(uint32_t saddr, const void* gaddr, uint32_t srcsz) {
    asm volatile("cp.async.cg.shared.global [%0], [%1], 16, %2;"
                 :: "r"(saddr), "l"(gaddr), "r"(srcsz) : "memory");
}
__device__ __forceinline__ void cp_commit() {
    asm volatile("cp.async.commit_group;" ::: "memory");
}
__device__ __forceinline__ void cp_wait2() {
    asm volatile("cp.async.wait_group 2;" ::: "memory");
}
__device__ __forceinline__ void ldsm_x4(uint32_t* r, uint32_t addr) {
    asm volatile("ldmatrix.sync.aligned.m8n8.x4.shared.b16 {%0,%1,%2,%3}, [%4];"
                 : "=r"(r[0]), "=r"(r[1]), "=r"(r[2]), "=r"(r[3]) : "r"(addr));
}
__device__ __forceinline__ void mma16816(float* c, const uint32_t* a, const uint32_t* b) {
    asm volatile(
        "mma.sync.aligned.m16n8k16.row.col.f32.bf16.bf16.f32 "
        "{%0,%1,%2,%3}, {%4,%5,%6,%7}, {%8,%9}, {%0,%1,%2,%3};"
        : "+f"(c[0]), "+f"(c[1]), "+f"(c[2]), "+f"(c[3])
        : "r"(a[0]), "r"(a[1]), "r"(a[2]), "r"(a[3]), "r"(b[0]), "r"(b[1]));
}

// ---------------- fused fp32 -> bf16 hi/lo split for x, w1, w2 --------------
#define N4X  (ML * DIMM / 4)            // 524288
#define N4W1 (D_IN_PROJ * DIMM / 4)     // 1083392
#define N4W2 (DIMM * D_INNER / 4)       // 524288
__global__ __launch_bounds__(256) void split_all(
    const float* __restrict__ x, const float* __restrict__ w1,
    const float* __restrict__ w2)
{
    int i = blockIdx.x * 256 + threadIdx.x;
    const float* s;
    __nv_bfloat16 *hi, *lo;
    int j;
    if (i < N4X) { s = x; hi = g_xhi; lo = g_xlo; j = i; }
    else if (i < N4X + N4W1) { s = w1; hi = g_w1hi; lo = g_w1lo; j = i - N4X; }
    else if (i < N4X + N4W1 + N4W2) { s = w2; hi = g_w2hi; lo = g_w2lo; j = i - N4X - N4W1; }
    else return;

    float4 v = reinterpret_cast<const float4*>(s)[j];
    __nv_bfloat16 h0 = __float2bfloat16(v.x);
    __nv_bfloat16 h1 = __float2bfloat16(v.y);
    __nv_bfloat16 h2 = __float2bfloat16(v.z);
    __nv_bfloat16 h3 = __float2bfloat16(v.w);
    __nv_bfloat16 l0 = __float2bfloat16(v.x - __bfloat162float(h0));
    __nv_bfloat16 l1 = __float2bfloat16(v.y - __bfloat162float(h1));
    __nv_bfloat16 l2 = __float2bfloat16(v.z - __bfloat162float(h2));
    __nv_bfloat16 l3 = __float2bfloat16(v.w - __bfloat162float(h3));
    __nv_bfloat162 hh0{h0, h1}, hh1{h2, h3}, ll0{l0, l1}, ll1{l2, l3};
    reinterpret_cast<__nv_bfloat162*>(hi)[j * 2 + 0] = hh0;
    reinterpret_cast<__nv_bfloat162*>(hi)[j * 2 + 1] = hh1;
    reinterpret_cast<__nv_bfloat162*>(lo)[j * 2 + 0] = ll0;
    reinterpret_cast<__nv_bfloat162*>(lo)[j * 2 + 1] = ll1;
}

// ---------------- mma.sync GEMM (bf16x3, 3-stage cp.async pipeline) ---------
// CTA: 128x128 tile, BK=64, 256 threads = 8 warps (2M x 4N), warp tile 64x32.
// smem per stage: Ah,Al,Bh,Bl each 128x64 bf16 = 16KB -> 64KB; 3 stages = 192KB.
#define TSZ 16384
__global__ __launch_bounds__(256, 1) void gemm_mma(
    const __nv_bfloat16* __restrict__ Ahi, const __nv_bfloat16* __restrict__ Alo,
    const __nv_bfloat16* __restrict__ Bhi, const __nv_bfloat16* __restrict__ Blo,
    float* __restrict__ C, int M, int N, int K)
{
    extern __shared__ char smem[];
    const int tid  = threadIdx.x;
    const int wid  = tid >> 5;
    const int lane = tid & 31;
    const int bm = blockIdx.y * 128, bn = blockIdx.x * 128;
    const int wm = (wid >> 2) * 64;
    const int wn = (wid & 3) * 32;

    const uint32_t sbase = smem_u32(smem);

    float acc[4][4][4];
#pragma unroll
    for (int mi = 0; mi < 4; mi++)
#pragma unroll
        for (int ni = 0; ni < 4; ni++)
#pragma unroll
            for (int v = 0; v < 4; v++) acc[mi][ni][v] = 0.f;

    const int NC = K >> 6;

    auto load_stage = [&](int buf, int k0) {
        uint32_t st = sbase + buf * 4 * TSZ;
#pragma unroll
        for (int it = 0; it < 4; it++) {
            int cid = it * 256 + tid;
            int r = cid >> 3, j = cid & 7;
            uint32_t swz = (uint32_t)((r * 8 + (j ^ (r & 7))) * 16);
            size_t aoff = (size_t)(bm + r) * K + k0 + j * 8;
            cp_async16(st + swz,           Ahi + aoff, 16);
            cp_async16(st + TSZ + swz,     Alo + aoff, 16);
            int n = bn + r;
            uint32_t ok = (n < N) ? 16u : 0u;
            size_t boff = (size_t)(ok ? n : 0) * K + k0 + j * 8;
            cp_async16(st + 2 * TSZ + swz, Bhi + boff, ok);
            cp_async16(st + 3 * TSZ + swz, Blo + boff, ok);
        }
    };

    load_stage(0, 0);  cp_commit();
    load_stage(1, 64); cp_commit();

    const int rA = wm + (lane & 15);
    const int jA = lane >> 4;
    const int qB = lane >> 3;
    const int rB = wn + ((qB >= 2) ? 8 : 0) + (lane & 7);
    const int jB = qB & 1;

    int buf = 0;
    for (int ch = 0; ch < NC; ch++) {
        if (ch + 2 < NC) load_stage((buf + 2 >= 3) ? buf - 1 : buf + 2, (ch + 2) << 6);
        cp_commit();
        cp_wait2();
        __syncthreads();

        uint32_t stA  = sbase + buf * 4 * TSZ;
        uint32_t stAl = stA + TSZ;
        uint32_t stB  = stA + 2 * TSZ;
        uint32_t stBl = stA + 3 * TSZ;

#pragma unroll
        for (int ks = 0; ks < 4; ks++) {
            // B fragments for this ks (4 ldsm)
            uint32_t bh[2][4], bl[2][4];
#pragma unroll
            for (int np = 0; np < 2; np++) {
                int r = rB + np * 16;
                int jj = 2 * ks + jB;
                uint32_t off = (uint32_t)((r * 8 + (jj ^ (r & 7))) * 16);
                ldsm_x4(bh[np], stB  + off);
                ldsm_x4(bl[np], stBl + off);
            }
            // per-mi: 2 ldsm then 12 MMAs -> loads of mi+1 overlap MMAs of mi
#pragma unroll
            for (int mi = 0; mi < 4; mi++) {
                uint32_t ah[4], al[4];
                int r = rA + mi * 16;
                int jj = 2 * ks + jA;
                uint32_t off = (uint32_t)((r * 8 + (jj ^ (r & 7))) * 16);
                ldsm_x4(ah, stA  + off);
                ldsm_x4(al, stAl + off);
#pragma unroll
                for (int ni = 0; ni < 4; ni++) {
                    const uint32_t* bfh = &bh[ni >> 1][(ni & 1) * 2];
                    const uint32_t* bfl = &bl[ni >> 1][(ni & 1) * 2];
                    mma16816(acc[mi][ni], ah, bfh);
                    mma16816(acc[mi][ni], ah, bfl);
                    mma16816(acc[mi][ni], al, bfh);
                }
            }
        }
        __syncthreads();
        buf = (buf + 1 >= 3) ? 0 : buf + 1;
    }

    const int gid = lane >> 2, tig = lane & 3;
#pragma unroll
    for (int mi = 0; mi < 4; mi++) {
        int row = bm + wm + mi * 16 + gid;
#pragma unroll
        for (int ni = 0; ni < 4; ni++) {
            int col = bn + wn + ni * 8 + tig * 2;
            if (col < N) {
                float2 lo2 = make_float2(acc[mi][ni][0], acc[mi][ni][1]);
                float2 hi2 = make_float2(acc[mi][ni][2], acc[mi][ni][3]);
                *reinterpret_cast<float2*>(C + (size_t)row * N + col) = lo2;
                *reinterpret_cast<float2*>(C + (size_t)(row + 8) * N + col) = hi2;
            }
        }
    }
}

// ---------------- depthwise causal conv(4) + silu, with abar fused ----------
// grid = ML*D_INNER/256 blocks; blocks [0,64) additionally compute a_bar.
__global__ __launch_bounds__(256) void conv_silu_abar_kernel(
    const float* __restrict__ conv_w, const float* __restrict__ conv_b,
    const float* __restrict__ A_log, const float* __restrict__ dt_bias)
{
    int idx = blockIdx.x * 256 + threadIdx.x;
    {
        int c  = idx & (D_INNER - 1);
        int ml = idx >> 11;
        int l  = ml & (SEQ - 1);
        int b  = ml >> 10;

        float acc = conv_b[c];
#pragma unroll
        for (int k = 0; k < D_CONV; k++) {
            int ls = l + k - (D_CONV - 1);
            if (ls >= 0)
                acc = fmaf(g_zx[(size_t)(b * SEQ + ls) * D_IN_PROJ + D_INNER + c],
                           conv_w[c * D_CONV + k], acc);
        }
        acc = acc / (1.f + expf(-acc));
        g_xconv[idx] = acc;
    }
    if (blockIdx.x < (ML * N_HEADS) / 256) {
        int i2 = blockIdx.x * 256 + threadIdx.x;   // over ML*N_HEADS
        int h  = i2 & (N_HEADS - 1);
        int ml = i2 >> 3;
        float raw = g_zx[(size_t)ml * D_IN_PROJ + 2 * D_INNER + h] + dt_bias[h];
        float sp  = (raw > 20.f) ? raw : log1pf(expf(raw));
        g_abar[i2] = expf(-expf(A_log[h]) * sp);
    }
}

// ---------------- per-segment decay products --------------------------------
__global__ __launch_bounds__(128) void aseg_kernel()
{
    int tid = threadIdx.x;             // = (b*8+h)*8 + seg
    int seg = tid & 7;
    int h   = (tid >> 3) & 7;
    int b   = tid >> 6;
    float p = 1.f;
    int t0 = seg * SEG_LEN;
#pragma unroll 8
    for (int t = 0; t < SEG_LEN; t++)
        p *= g_abar[(b * SEQ + t0 + t) * N_HEADS + h];
    g_aseg[tid] = p;
}

// ---------------- scan pass A: per-segment local state (zero init) ----------
// grid 1024: (b,h,seg,dq). 128 threads: 4/d (q=state quarter), 32 d per CTA.
__global__ __launch_bounds__(128) void scan_partA()
{
    const int bx = blockIdx.x;
    const int dq = bx & 7, seg = (bx >> 3) & 7, h = (bx >> 6) & 7, b = bx >> 9;
    const int tid = threadIdx.x;
    const int q  = tid & 3;
    const int dl = tid >> 2;
    const int c0 = h * HEAD_DIM + dq * 32;

    float hs[16];
#pragma unroll
    for (int n = 0; n < 16; n++) hs[n] = 0.f;

    __shared__ float sB[2][4][64];
    __shared__ float sx[2][4][32];
    __shared__ float sa[2][4];

    const size_t rb = (size_t)b * SEQ + seg * SEG_LEN;

    auto load_group = [&](int g, int bb) {
        const int t0 = g * 4;
        if (tid < 64) {
            int st = tid >> 4, f = tid & 15;
            const float* p = g_zx + (rb + t0 + st) * D_IN_PROJ + 2 * D_INNER + N_HEADS + f * 4;
            *reinterpret_cast<float4*>(&sB[bb][st][f * 4]) = *reinterpret_cast<const float4*>(p);
        }
        { int st = tid >> 5, ii = tid & 31;
          sx[bb][st][ii] = g_xconv[(rb + t0 + st) * D_INNER + c0 + ii]; }
        if (tid < 4) sa[bb][tid] = g_abar[(rb + t0 + tid) * N_HEADS + h];
    };

    load_group(0, 0);
    __syncthreads();

    for (int g = 0; g < SEG_LEN / 4; g++) {
        const int bb = g & 1;
        if (g + 1 < SEG_LEN / 4) load_group(g + 1, bb ^ 1);
#pragma unroll
        for (int st = 0; st < 4; st++) {
            float a = sa[bb][st];
            float x = sx[bb][st][dl];
            const float4* Bv = reinterpret_cast<const float4*>(&sB[bb][st][q * 16]);
#pragma unroll
            for (int i = 0; i < 4; i++) {
                float4 bq = Bv[i];
                hs[i*4+0] = fmaf(a, hs[i*4+0], bq.x * x);
                hs[i*4+1] = fmaf(a, hs[i*4+1], bq.y * x);
                hs[i*4+2] = fmaf(a, hs[i*4+2], bq.z * x);
                hs[i*4+3] = fmaf(a, hs[i*4+3], bq.w * x);
            }
        }
        __syncthreads();
    }

    size_t base = (((size_t)(b * 8 + h) * 8 + seg) * (HEAD_DIM * D_STATE))
                + (size_t)(dq * 32 + dl) * 64 + q * 16;
#pragma unroll
    for (int i = 0; i < 4; i++)
        *reinterpret_cast<float4*>(&g_state[base + i * 4]) =
            make_float4(hs[i*4+0], hs[i*4+1], hs[i*4+2], hs[i*4+3]);
}

// ---------------- scan pass C: inline combine + local scan + y + gate -------
__global__ __launch_bounds__(128) void scan_partC(const float* __restrict__ D_param)
{
    const int bx = blockIdx.x;
    const int dq = bx & 7, seg = (bx >> 3) & 7, h = (bx >> 6) & 7, b = bx >> 9;
    const int tid = threadIdx.x;
    const int q  = tid & 3;
    const int dl = tid >> 2;
    const int c0 = h * HEAD_DIM + dq * 32;
    const int c  = c0 + dl;
    const int bh = b * 8 + h;

    // init state = H_seg = sum_{s<seg} (prod_{j=s+1}^{seg-1} A_j) * state_s
    float hs[16];
#pragma unroll
    for (int n = 0; n < 16; n++) hs[n] = 0.f;
    if (seg > 0) {
        float f = 1.f;
        const size_t slice = (size_t)(dq * 32 + dl) * 64 + q * 16;
        for (int s = seg - 1; s >= 0; s--) {
            size_t base = ((size_t)bh * 8 + s) * (HEAD_DIM * D_STATE) + slice;
#pragma unroll
            for (int i = 0; i < 4; i++) {
                float4 v = *reinterpret_cast<const float4*>(&g_state[base + i * 4]);
                hs[i*4+0] = fmaf(f, v.x, hs[i*4+0]);
                hs[i*4+1] = fmaf(f, v.y, hs[i*4+1]);
                hs[i*4+2] = fmaf(f, v.z, hs[i*4+2]);
                hs[i*4+3] = fmaf(f, v.w, hs[i*4+3]);
            }
            f *= g_aseg[bh * 8 + s];
        }
    }

    __shared__ float sBC[2][4][128];
    __shared__ float sx[2][4][32];
    __shared__ float sz[2][4][32];
    __shared__ float sa[2][4];

    const float Dp = D_param[h];
    const size_t rb = (size_t)b * SEQ + seg * SEG_LEN;

    auto load_group = [&](int g, int bb) {
        const int t0 = g * 4;
        {   int st = tid >> 5, f4 = tid & 31;
            const float* p = g_zx + (rb + t0 + st) * D_IN_PROJ + 2 * D_INNER + N_HEADS + f4 * 4;
            *reinterpret_cast<float4*>(&sBC[bb][st][f4 * 4]) = *reinterpret_cast<const float4*>(p); }
        {   int st = tid >> 5, ii = tid & 31;
            sx[bb][st][ii] = g_xconv[(rb + t0 + st) * D_INNER + c0 + ii];
            sz[bb][st][ii] = g_zx[(rb + t0 + st) * D_IN_PROJ + c0 + ii]; }
        if (tid < 4) sa[bb][tid] = g_abar[(rb + t0 + tid) * N_HEADS + h];
    };

    load_group(0, 0);
    __syncthreads();

    for (int g = 0; g < SEG_LEN / 4; g++) {
        const int bb = g & 1;
        if (g + 1 < SEG_LEN / 4) load_group(g + 1, bb ^ 1);
#pragma unroll
        for (int st = 0; st < 4; st++) {
            float a = sa[bb][st];
            float x = sx[bb][st][dl];
            const float4* Bv = reinterpret_cast<const float4*>(&sBC[bb][st][q * 16]);
            const float4* Cv = reinterpret_cast<const float4*>(&sBC[bb][st][64 + q * 16]);
            float y = 0.f;
#pragma unroll
            for (int i = 0; i < 4; i++) {
                float4 bq = Bv[i], cq = Cv[i];
                hs[i*4+0] = fmaf(a, hs[i*4+0], bq.x * x); y = fmaf(hs[i*4+0], cq.x, y);
                hs[i*4+1] = fmaf(a, hs[i*4+1], bq.y * x); y = fmaf(hs[i*4+1], cq.y, y);
                hs[i*4+2] = fmaf(a, hs[i*4+2], bq.z * x); y = fmaf(hs[i*4+2], cq.z, y);
                hs[i*4+3] = fmaf(a, hs[i*4+3], bq.w * x); y = fmaf(hs[i*4+3], cq.w, y);
            }
            y += __shfl_xor_sync(0xFFFFFFFFu, y, 1);
            y += __shfl_xor_sync(0xFFFFFFFFu, y, 2);
            if (q == 0) {
                float zv = sz[bb][st][dl];
                float gate = zv / (1.f + expf(-zv));
                g_y[(rb + g * 4 + st) * D_INNER + c] = (y + Dp * x) * gate;
            }
        }
        __syncthreads();
    }
}

// ---------------- rmsnorm + bf16 hi/lo split fused ---------------------------
__global__ __launch_bounds__(256) void rmsnorm_split_kernel(const float* __restrict__ norm_w)
{
    const int row = blockIdx.x;
    const float* y = g_y + (size_t)row * D_INNER;
    float4 v[2];
    float s = 0.f;
#pragma unroll
    for (int it = 0; it < 2; it++) {
        v[it] = reinterpret_cast<const float4*>(y)[threadIdx.x + it * 256];
        s = fmaf(v[it].x, v[it].x, s);
        s = fmaf(v[it].y, v[it].y, s);
        s = fmaf(v[it].z, v[it].z, s);
        s = fmaf(v[it].w, v[it].w, s);
    }
#pragma unroll
    for (int o = 16; o; o >>= 1) s += __shfl_xor_sync(0xFFFFFFFFu, s, o);
    __shared__ float red[8];
    if ((threadIdx.x & 31) == 0) red[threadIdx.x >> 5] = s;
    __syncthreads();
    if (threadIdx.x < 8) {
        s = red[threadIdx.x];
#pragma unroll
        for (int o = 4; o; o >>= 1) s += __shfl_xor_sync(0xFFu, s, o);
        if (threadIdx.x == 0) red[0] = s;
    }
    __syncthreads();
    const float scale = rsqrtf(red[0] * (1.f / D_INNER) + 1e-6f);

    __nv_bfloat16* hi = g_yhi + (size_t)row * D_INNER;
    __nv_bfloat16* lo = g_ylo + (size_t)row * D_INNER;
#pragma unroll
    for (int it = 0; it < 2; it++) {
        int i4 = threadIdx.x + it * 256;
        float4 w = reinterpret_cast<const float4*>(norm_w)[i4];
        float f0 = v[it].x * scale * w.x;
        float f1 = v[it].y * scale * w.y;
        float f2 = v[it].z * scale * w.z;
        float f3 = v[it].w * scale * w.w;
        __nv_bfloat16 h0 = __float2bfloat16(f0);
        __nv_bfloat16 h1 = __float2bfloat16(f1);
        __nv_bfloat16 h2 = __float2bfloat16(f2);
        __nv_bfloat16 h3 = __float2bfloat16(f3);
        __nv_bfloat16 l0 = __float2bfloat16(f0 - __bfloat162float(h0));
        __nv_bfloat16 l1 = __float2bfloat16(f1 - __bfloat162float(h1));
        __nv_bfloat16 l2 = __float2bfloat16(f2 - __bfloat162float(h2));
        __nv_bfloat16 l3 = __float2bfloat16(f3 - __bfloat162float(h3));
        __nv_bfloat162 hh0{h0, h1}, hh1{h2, h3}, ll0{l0, l1}, ll1{l2, l3};
        reinterpret_cast<__nv_bfloat162*>(hi)[i4 * 2 + 0] = hh0;
        reinterpret_cast<__nv_bfloat162*>(hi)[i4 * 2 + 1] = hh1;
        reinterpret_cast<__nv_bfloat162*>(lo)[i4 * 2 + 0] = ll0;
        reinterpret_cast<__nv_bfloat162*>(lo)[i4 * 2 + 1] = ll1;
    }
}

// ---------------- launch ----------------------------------------------------
extern "C" void kernel_launch(void* const* d_in, const int* in_sizes, int n_in,
                              void* d_out, int out_size)
{
    const float* x          = (const float*)d_in[0];
    const float* in_proj_w  = (const float*)d_in[1];
    const float* conv_w     = (const float*)d_in[2];
    const float* conv_b     = (const float*)d_in[3];
    const float* A_log      = (const float*)d_in[4];
    const float* D_param    = (const float*)d_in[5];
    const float* dt_bias    = (const float*)d_in[6];
    const float* norm_w     = (const float*)d_in[7];
    const float* out_proj_w = (const float*)d_in[8];
    float* out = (float*)d_out;

    float *p_zx;
    __nv_bfloat16 *p_xhi, *p_xlo, *p_w1hi, *p_w1lo, *p_yhi, *p_ylo, *p_w2hi, *p_w2lo;
    cudaGetSymbolAddress((void**)&p_zx,   g_zx);
    cudaGetSymbolAddress((void**)&p_xhi,  g_xhi);
    cudaGetSymbolAddress((void**)&p_xlo,  g_xlo);
    cudaGetSymbolAddress((void**)&p_w1hi, g_w1hi);
    cudaGetSymbolAddress((void**)&p_w1lo, g_w1lo);
    cudaGetSymbolAddress((void**)&p_yhi,  g_yhi);
    cudaGetSymbolAddress((void**)&p_ylo,  g_ylo);
    cudaGetSymbolAddress((void**)&p_w2hi, g_w2hi);
    cudaGetSymbolAddress((void**)&p_w2lo, g_w2lo);

    const int dyn_smem = 12 * TSZ;   // 192KB (3 stages)
    cudaFuncSetAttribute(gemm_mma, cudaFuncAttributeMaxDynamicSharedMemorySize, dyn_smem);

    // 0. split all fp32 inputs to bf16 hi/lo (one launch)
    {
        int total = N4X + N4W1 + N4W2;
        split_all<<<(total + 255) / 256, 256>>>(x, in_proj_w, out_proj_w);
    }
    // 1. in_proj
    {
        dim3 grid((D_IN_PROJ + 127) / 128, ML / 128);
        gemm_mma<<<grid, 256, dyn_smem>>>(p_xhi, p_xlo, p_w1hi, p_w1lo,
                                          p_zx, ML, D_IN_PROJ, DIMM);
    }
    // 2. conv + silu (+ a_bar fused into first 64 blocks)
    conv_silu_abar_kernel<<<(ML * D_INNER) / 256, 256>>>(conv_w, conv_b, A_log, dt_bias);
    // 3. segment decay products
    aseg_kernel<<<1, 128>>>();
    // 4. two-level scan (combine inlined into pass C)
    scan_partA<<<1024, 128>>>();
    scan_partC<<<1024, 128>>>(D_param);
    // 5. rmsnorm + y split fused
    rmsnorm_split_kernel<<<ML, 256>>>(norm_w);
    // 6. out_proj
    {
        dim3 grid(DIMM / 128, ML / 128);
        gemm_mma<<<grid, 256, dyn_smem>>>(p_yhi, p_ylo, p_w2hi, p_w2lo,
                                          out, ML, DIMM, D_INNER);
    }
}

// round 7
// speedup vs baseline: 3.5861x; 1.0108x over previous
#include <cuda_runtime.h>
#include <cuda_bf16.h>
#include <math.h>
#include <stdint.h>

#define BATCH    2
#define SEQ      1024
#define DIMM     1024
#define D_STATE  64
#define D_CONV   4
#define N_HEADS  8
#define D_INNER  2048
#define HEAD_DIM 256
#define D_IN_PROJ 4232          // 2048 + 2048 + 8 + 64 + 64
#define ML       (BATCH*SEQ)    // 2048
#define NSEG     8
#define SEG_LEN  128            // SEQ / NSEG

// ---------------- scratch (device globals: allocation-free) ----------------
__device__ float g_zx[(size_t)ML * D_IN_PROJ];      // in_proj output
__device__ float g_xconv[(size_t)ML * D_INNER];     // silu(conv(xc)) == xh
__device__ float g_y[(size_t)ML * D_INNER];         // (y+Dx)*silu(z)
__device__ float g_abar[ML * N_HEADS];
__device__ float g_aseg[BATCH * N_HEADS * NSEG];    // per-segment decay product
__device__ float g_state[(size_t)BATCH * N_HEADS * NSEG * HEAD_DIM * D_STATE]; // 8MB

// bf16 hi/lo split buffers
__device__ __nv_bfloat16 g_xhi[(size_t)ML * DIMM];
__device__ __nv_bfloat16 g_xlo[(size_t)ML * DIMM];
__device__ __nv_bfloat16 g_w1hi[(size_t)D_IN_PROJ * DIMM];
__device__ __nv_bfloat16 g_w1lo[(size_t)D_IN_PROJ * DIMM];
__device__ __nv_bfloat16 g_yhi[(size_t)ML * D_INNER];
__device__ __nv_bfloat16 g_ylo[(size_t)ML * D_INNER];
__device__ __nv_bfloat16 g_w2hi[(size_t)DIMM * D_INNER];
__device__ __nv_bfloat16 g_w2lo[(size_t)DIMM * D_INNER];

// ---------------- PTX helpers (sm_80-era, compute_103-safe) ----------------
__device__ __forceinline__ uint32_t smem_u32(const void* p) {
    uint32_t a;
    asm("{ .reg .u64 t; cvta.to.shared.u64 t, %1; cvt.u32.u64 %0, t; }"
        : "=r"(a) : "l"(p));
    return a;
}
__device__ __forceinline__ void cp_async16(uint32_t saddr, const void* gaddr, uint32_t srcsz) {
    asm volatile("cp.async.cg.shared.global [%0], [%1], 16, %2;"
                 :: "r"(saddr), "l"(gaddr), "r"(srcsz) : "memory");
}
__device__ __forceinline__ void cp_commit() {
    asm volatile("cp.async.commit_group;" ::: "memory");
}
__device__ __forceinline__ void cp_wait2() {
    asm volatile("cp.async.wait_group 2;" ::: "memory");
}
__device__ __forceinline__ void ldsm_x4(uint32_t* r, uint32_t addr) {
    asm volatile("ldmatrix.sync.aligned.m8n8.x4.shared.b16 {%0,%1,%2,%3}, [%4];"
                 : "=r"(r[0]), "=r"(r[1]), "=r"(r[2]), "=r"(r[3]) : "r"(addr));
}
__device__ __forceinline__ void mma16816(float* c, const uint32_t* a, const uint32_t* b) {
    asm volatile(
        "mma.sync.aligned.m16n8k16.row.col.f32.bf16.bf16.f32 "
        "{%0,%1,%2,%3}, {%4,%5,%6,%7}, {%8,%9}, {%0,%1,%2,%3};"
        : "+f"(c[0]), "+f"(c[1]), "+f"(c[2]), "+f"(c[3])
        : "r"(a[0]), "r"(a[1]), "r"(a[2]), "r"(a[3]), "r"(b[0]), "r"(b[1]));
}

// ---------------- fused fp32 -> bf16 hi/lo split for x, w1, w2 --------------
#define N4X  (ML * DIMM / 4)            // 524288
#define N4W1 (D_IN_PROJ * DIMM / 4)     // 1083392
#define N4W2 (DIMM * D_INNER / 4)       // 524288
__global__ __launch_bounds__(256) void split_all(
    const float* __restrict__ x, const float* __restrict__ w1,
    const float* __restrict__ w2)
{
    int i = blockIdx.x * 256 + threadIdx.x;
    const float* s;
    __nv_bfloat16 *hi, *lo;
    int j;
    if (i < N4X) { s = x; hi = g_xhi; lo = g_xlo; j = i; }
    else if (i < N4X + N4W1) { s = w1; hi = g_w1hi; lo = g_w1lo; j = i - N4X; }
    else if (i < N4X + N4W1 + N4W2) { s = w2; hi = g_w2hi; lo = g_w2lo; j = i - N4X - N4W1; }
    else return;

    float4 v = reinterpret_cast<const float4*>(s)[j];
    __nv_bfloat16 h0 = __float2bfloat16(v.x);
    __nv_bfloat16 h1 = __float2bfloat16(v.y);
    __nv_bfloat16 h2 = __float2bfloat16(v.z);
    __nv_bfloat16 h3 = __float2bfloat16(v.w);
    __nv_bfloat16 l0 = __float2bfloat16(v.x - __bfloat162float(h0));
    __nv_bfloat16 l1 = __float2bfloat16(v.y - __bfloat162float(h1));
    __nv_bfloat16 l2 = __float2bfloat16(v.z - __bfloat162float(h2));
    __nv_bfloat16 l3 = __float2bfloat16(v.w - __bfloat162float(h3));
    __nv_bfloat162 hh0{h0, h1}, hh1{h2, h3}, ll0{l0, l1}, ll1{l2, l3};
    reinterpret_cast<__nv_bfloat162*>(hi)[j * 2 + 0] = hh0;
    reinterpret_cast<__nv_bfloat162*>(hi)[j * 2 + 1] = hh1;
    reinterpret_cast<__nv_bfloat162*>(lo)[j * 2 + 0] = ll0;
    reinterpret_cast<__nv_bfloat162*>(lo)[j * 2 + 1] = ll1;
}

// ---------------- mma.sync GEMM (bf16x3, 3-stage cp.async pipeline) ---------
// CTA: 128x128 tile, BK=64, 256 threads = 8 warps (2M x 4N), warp tile 64x32.
// MMA issue order is term-major per mi so same-accumulator reuse distance is
// 4 MMAs (breaks the HMMA RAW chain).
#define TSZ 16384
__global__ __launch_bounds__(256, 1) void gemm_mma(
    const __nv_bfloat16* __restrict__ Ahi, const __nv_bfloat16* __restrict__ Alo,
    const __nv_bfloat16* __restrict__ Bhi, const __nv_bfloat16* __restrict__ Blo,
    float* __restrict__ C, int M, int N, int K)
{
    extern __shared__ char smem[];
    const int tid  = threadIdx.x;
    const int wid  = tid >> 5;
    const int lane = tid & 31;
    const int bm = blockIdx.y * 128, bn = blockIdx.x * 128;
    const int wm = (wid >> 2) * 64;
    const int wn = (wid & 3) * 32;

    const uint32_t sbase = smem_u32(smem);

    float acc[4][4][4];
#pragma unroll
    for (int mi = 0; mi < 4; mi++)
#pragma unroll
        for (int ni = 0; ni < 4; ni++)
#pragma unroll
            for (int v = 0; v < 4; v++) acc[mi][ni][v] = 0.f;

    const int NC = K >> 6;

    auto load_stage = [&](int buf, int k0) {
        uint32_t st = sbase + buf * 4 * TSZ;
#pragma unroll
        for (int it = 0; it < 4; it++) {
            int cid = it * 256 + tid;
            int r = cid >> 3, j = cid & 7;
            uint32_t swz = (uint32_t)((r * 8 + (j ^ (r & 7))) * 16);
            size_t aoff = (size_t)(bm + r) * K + k0 + j * 8;
            cp_async16(st + swz,           Ahi + aoff, 16);
            cp_async16(st + TSZ + swz,     Alo + aoff, 16);
            int n = bn + r;
            uint32_t ok = (n < N) ? 16u : 0u;
            size_t boff = (size_t)(ok ? n : 0) * K + k0 + j * 8;
            cp_async16(st + 2 * TSZ + swz, Bhi + boff, ok);
            cp_async16(st + 3 * TSZ + swz, Blo + boff, ok);
        }
    };

    load_stage(0, 0);  cp_commit();
    load_stage(1, 64); cp_commit();

    const int rA = wm + (lane & 15);
    const int jA = lane >> 4;
    const int qB = lane >> 3;
    const int rB = wn + ((qB >= 2) ? 8 : 0) + (lane & 7);
    const int jB = qB & 1;

    int buf = 0;
    for (int ch = 0; ch < NC; ch++) {
        if (ch + 2 < NC) load_stage((buf + 2 >= 3) ? buf - 1 : buf + 2, (ch + 2) << 6);
        cp_commit();
        cp_wait2();
        __syncthreads();

        uint32_t stA  = sbase + buf * 4 * TSZ;
        uint32_t stAl = stA + TSZ;
        uint32_t stB  = stA + 2 * TSZ;
        uint32_t stBl = stA + 3 * TSZ;

#pragma unroll
        for (int ks = 0; ks < 4; ks++) {
            // B fragments for this ks (4 ldsm)
            uint32_t bh[2][4], bl[2][4];
#pragma unroll
            for (int np = 0; np < 2; np++) {
                int r = rB + np * 16;
                int jj = 2 * ks + jB;
                uint32_t off = (uint32_t)((r * 8 + (jj ^ (r & 7))) * 16);
                ldsm_x4(bh[np], stB  + off);
                ldsm_x4(bl[np], stBl + off);
            }
            // per-mi: 2 ldsm, then 3 term-major sweeps of 4 MMAs
#pragma unroll
            for (int mi = 0; mi < 4; mi++) {
                uint32_t ah[4], al[4];
                int r = rA + mi * 16;
                int jj = 2 * ks + jA;
                uint32_t off = (uint32_t)((r * 8 + (jj ^ (r & 7))) * 16);
                ldsm_x4(ah, stA  + off);
                ldsm_x4(al, stAl + off);
#pragma unroll
                for (int ni = 0; ni < 4; ni++)
                    mma16816(acc[mi][ni], ah, &bh[ni >> 1][(ni & 1) * 2]);
#pragma unroll
                for (int ni = 0; ni < 4; ni++)
                    mma16816(acc[mi][ni], ah, &bl[ni >> 1][(ni & 1) * 2]);
#pragma unroll
                for (int ni = 0; ni < 4; ni++)
                    mma16816(acc[mi][ni], al, &bh[ni >> 1][(ni & 1) * 2]);
            }
        }
        __syncthreads();
        buf = (buf + 1 >= 3) ? 0 : buf + 1;
    }

    const int gid = lane >> 2, tig = lane & 3;
#pragma unroll
    for (int mi = 0; mi < 4; mi++) {
        int row = bm + wm + mi * 16 + gid;
#pragma unroll
        for (int ni = 0; ni < 4; ni++) {
            int col = bn + wn + ni * 8 + tig * 2;
            if (col < N) {
                float2 lo2 = make_float2(acc[mi][ni][0], acc[mi][ni][1]);
                float2 hi2 = make_float2(acc[mi][ni][2], acc[mi][ni][3]);
                *reinterpret_cast<float2*>(C + (size_t)row * N + col) = lo2;
                *reinterpret_cast<float2*>(C + (size_t)(row + 8) * N + col) = hi2;
            }
        }
    }
}

// ---------------- depthwise causal conv(4) + silu, with abar fused ----------
__global__ __launch_bounds__(256) void conv_silu_abar_kernel(
    const float* __restrict__ conv_w, const float* __restrict__ conv_b,
    const float* __restrict__ A_log, const float* __restrict__ dt_bias)
{
    int idx = blockIdx.x * 256 + threadIdx.x;
    {
        int c  = idx & (D_INNER - 1);
        int ml = idx >> 11;
        int l  = ml & (SEQ - 1);
        int b  = ml >> 10;

        float acc = conv_b[c];
#pragma unroll
        for (int k = 0; k < D_CONV; k++) {
            int ls = l + k - (D_CONV - 1);
            if (ls >= 0)
                acc = fmaf(g_zx[(size_t)(b * SEQ + ls) * D_IN_PROJ + D_INNER + c],
                           conv_w[c * D_CONV + k], acc);
        }
        acc = acc / (1.f + expf(-acc));
        g_xconv[idx] = acc;
    }
    if (blockIdx.x < (ML * N_HEADS) / 256) {
        int i2 = blockIdx.x * 256 + threadIdx.x;   // over ML*N_HEADS
        int h  = i2 & (N_HEADS - 1);
        int ml = i2 >> 3;
        float raw = g_zx[(size_t)ml * D_IN_PROJ + 2 * D_INNER + h] + dt_bias[h];
        float sp  = (raw > 20.f) ? raw : log1pf(expf(raw));
        g_abar[i2] = expf(-expf(A_log[h]) * sp);
    }
}

// ---------------- per-segment decay products (parallel: 1 warp/tuple) -------
// grid 16 x 256 threads = 128 warps = one per (b,h,seg).
__global__ __launch_bounds__(256) void aseg_kernel()
{
    int w = blockIdx.x * 8 + (threadIdx.x >> 5);    // 0..127
    int lane = threadIdx.x & 31;
    int seg = w & 7;
    int h   = (w >> 3) & 7;
    int b   = w >> 6;
    int t0  = seg * SEG_LEN;
    float p = 1.f;
#pragma unroll
    for (int k = 0; k < 4; k++)
        p *= g_abar[(b * SEQ + t0 + lane * 4 + k) * N_HEADS + h];
#pragma unroll
    for (int o = 16; o; o >>= 1)
        p *= __shfl_xor_sync(0xFFFFFFFFu, p, o);
    if (lane == 0) g_aseg[w] = p;
}

// ---------------- scan pass A: per-segment local state (zero init) ----------
__global__ __launch_bounds__(128) void scan_partA()
{
    const int bx = blockIdx.x;
    const int dq = bx & 7, seg = (bx >> 3) & 7, h = (bx >> 6) & 7, b = bx >> 9;
    const int tid = threadIdx.x;
    const int q  = tid & 3;
    const int dl = tid >> 2;
    const int c0 = h * HEAD_DIM + dq * 32;

    float hs[16];
#pragma unroll
    for (int n = 0; n < 16; n++) hs[n] = 0.f;

    __shared__ float sB[2][4][64];
    __shared__ float sx[2][4][32];
    __shared__ float sa[2][4];

    const size_t rb = (size_t)b * SEQ + seg * SEG_LEN;

    auto load_group = [&](int g, int bb) {
        const int t0 = g * 4;
        if (tid < 64) {
            int st = tid >> 4, f = tid & 15;
            const float* p = g_zx + (rb + t0 + st) * D_IN_PROJ + 2 * D_INNER + N_HEADS + f * 4;
            *reinterpret_cast<float4*>(&sB[bb][st][f * 4]) = *reinterpret_cast<const float4*>(p);
        }
        { int st = tid >> 5, ii = tid & 31;
          sx[bb][st][ii] = g_xconv[(rb + t0 + st) * D_INNER + c0 + ii]; }
        if (tid < 4) sa[bb][tid] = g_abar[(rb + t0 + tid) * N_HEADS + h];
    };

    load_group(0, 0);
    __syncthreads();

    for (int g = 0; g < SEG_LEN / 4; g++) {
        const int bb = g & 1;
        if (g + 1 < SEG_LEN / 4) load_group(g + 1, bb ^ 1);
#pragma unroll
        for (int st = 0; st < 4; st++) {
            float a = sa[bb][st];
            float x = sx[bb][st][dl];
            const float4* Bv = reinterpret_cast<const float4*>(&sB[bb][st][q * 16]);
#pragma unroll
            for (int i = 0; i < 4; i++) {
                float4 bq = Bv[i];
                hs[i*4+0] = fmaf(a, hs[i*4+0], bq.x * x);
                hs[i*4+1] = fmaf(a, hs[i*4+1], bq.y * x);
                hs[i*4+2] = fmaf(a, hs[i*4+2], bq.z * x);
                hs[i*4+3] = fmaf(a, hs[i*4+3], bq.w * x);
            }
        }
        __syncthreads();
    }

    size_t base = (((size_t)(b * 8 + h) * 8 + seg) * (HEAD_DIM * D_STATE))
                + (size_t)(dq * 32 + dl) * 64 + q * 16;
#pragma unroll
    for (int i = 0; i < 4; i++)
        *reinterpret_cast<float4*>(&g_state[base + i * 4]) =
            make_float4(hs[i*4+0], hs[i*4+1], hs[i*4+2], hs[i*4+3]);
}

// ---------------- scan pass C: inline combine + local scan + y + gate -------
__global__ __launch_bounds__(128) void scan_partC(const float* __restrict__ D_param)
{
    const int bx = blockIdx.x;
    const int dq = bx & 7, seg = (bx >> 3) & 7, h = (bx >> 6) & 7, b = bx >> 9;
    const int tid = threadIdx.x;
    const int q  = tid & 3;
    const int dl = tid >> 2;
    const int c0 = h * HEAD_DIM + dq * 32;
    const int c  = c0 + dl;
    const int bh = b * 8 + h;

    float hs[16];
#pragma unroll
    for (int n = 0; n < 16; n++) hs[n] = 0.f;
    if (seg > 0) {
        float f = 1.f;
        const size_t slice = (size_t)(dq * 32 + dl) * 64 + q * 16;
        for (int s = seg - 1; s >= 0; s--) {
            size_t base = ((size_t)bh * 8 + s) * (HEAD_DIM * D_STATE) + slice;
#pragma unroll
            for (int i = 0; i < 4; i++) {
                float4 v = *reinterpret_cast<const float4*>(&g_state[base + i * 4]);
                hs[i*4+0] = fmaf(f, v.x, hs[i*4+0]);
                hs[i*4+1] = fmaf(f, v.y, hs[i*4+1]);
                hs[i*4+2] = fmaf(f, v.z, hs[i*4+2]);
                hs[i*4+3] = fmaf(f, v.w, hs[i*4+3]);
            }
            f *= g_aseg[bh * 8 + s];
        }
    }

    __shared__ float sBC[2][4][128];
    __shared__ float sx[2][4][32];
    __shared__ float sz[2][4][32];
    __shared__ float sa[2][4];

    const float Dp = D_param[h];
    const size_t rb = (size_t)b * SEQ + seg * SEG_LEN;

    auto load_group = [&](int g, int bb) {
        const int t0 = g * 4;
        {   int st = tid >> 5, f4 = tid & 31;
            const float* p = g_zx + (rb + t0 + st) * D_IN_PROJ + 2 * D_INNER + N_HEADS + f4 * 4;
            *reinterpret_cast<float4*>(&sBC[bb][st][f4 * 4]) = *reinterpret_cast<const float4*>(p); }
        {   int st = tid >> 5, ii = tid & 31;
            sx[bb][st][ii] = g_xconv[(rb + t0 + st) * D_INNER + c0 + ii];
            sz[bb][st][ii] = g_zx[(rb + t0 + st) * D_IN_PROJ + c0 + ii]; }
        if (tid < 4) sa[bb][tid] = g_abar[(rb + t0 + tid) * N_HEADS + h];
    };

    load_group(0, 0);
    __syncthreads();

    for (int g = 0; g < SEG_LEN / 4; g++) {
        const int bb = g & 1;
        if (g + 1 < SEG_LEN / 4) load_group(g + 1, bb ^ 1);
#pragma unroll
        for (int st = 0; st < 4; st++) {
            float a = sa[bb][st];
            float x = sx[bb][st][dl];
            const float4* Bv = reinterpret_cast<const float4*>(&sBC[bb][st][q * 16]);
            const float4* Cv = reinterpret_cast<const float4*>(&sBC[bb][st][64 + q * 16]);
            float y = 0.f;
#pragma unroll
            for (int i = 0; i < 4; i++) {
                float4 bq = Bv[i], cq = Cv[i];
                hs[i*4+0] = fmaf(a, hs[i*4+0], bq.x * x); y = fmaf(hs[i*4+0], cq.x, y);
                hs[i*4+1] = fmaf(a, hs[i*4+1], bq.y * x); y = fmaf(hs[i*4+1], cq.y, y);
                hs[i*4+2] = fmaf(a, hs[i*4+2], bq.z * x); y = fmaf(hs[i*4+2], cq.z, y);
                hs[i*4+3] = fmaf(a, hs[i*4+3], bq.w * x); y = fmaf(hs[i*4+3], cq.w, y);
            }
            y += __shfl_xor_sync(0xFFFFFFFFu, y, 1);
            y += __shfl_xor_sync(0xFFFFFFFFu, y, 2);
            if (q == 0) {
                float zv = sz[bb][st][dl];
                float gate = zv / (1.f + expf(-zv));
                g_y[(rb + g * 4 + st) * D_INNER + c] = (y + Dp * x) * gate;
            }
        }
        __syncthreads();
    }
}

// ---------------- rmsnorm + bf16 hi/lo split fused ---------------------------
__global__ __launch_bounds__(256) void rmsnorm_split_kernel(const float* __restrict__ norm_w)
{
    const int row = blockIdx.x;
    const float* y = g_y + (size_t)row * D_INNER;
    float4 v[2];
    float s = 0.f;
#pragma unroll
    for (int it = 0; it < 2; it++) {
        v[it] = reinterpret_cast<const float4*>(y)[threadIdx.x + it * 256];
        s = fmaf(v[it].x, v[it].x, s);
        s = fmaf(v[it].y, v[it].y, s);
        s = fmaf(v[it].z, v[it].z, s);
        s = fmaf(v[it].w, v[it].w, s);
    }
#pragma unroll
    for (int o = 16; o; o >>= 1) s += __shfl_xor_sync(0xFFFFFFFFu, s, o);
    __shared__ float red[8];
    if ((threadIdx.x & 31) == 0) red[threadIdx.x >> 5] = s;
    __syncthreads();
    if (threadIdx.x < 8) {
        s = red[threadIdx.x];
#pragma unroll
        for (int o = 4; o; o >>= 1) s += __shfl_xor_sync(0xFFu, s, o);
        if (threadIdx.x == 0) red[0] = s;
    }
    __syncthreads();
    const float scale = rsqrtf(red[0] * (1.f / D_INNER) + 1e-6f);

    __nv_bfloat16* hi = g_yhi + (size_t)row * D_INNER;
    __nv_bfloat16* lo = g_ylo + (size_t)row * D_INNER;
#pragma unroll
    for (int it = 0; it < 2; it++) {
        int i4 = threadIdx.x + it * 256;
        float4 w = reinterpret_cast<const float4*>(norm_w)[i4];
        float f0 = v[it].x * scale * w.x;
        float f1 = v[it].y * scale * w.y;
        float f2 = v[it].z * scale * w.z;
        float f3 = v[it].w * scale * w.w;
        __nv_bfloat16 h0 = __float2bfloat16(f0);
        __nv_bfloat16 h1 = __float2bfloat16(f1);
        __nv_bfloat16 h2 = __float2bfloat16(f2);
        __nv_bfloat16 h3 = __float2bfloat16(f3);
        __nv_bfloat16 l0 = __float2bfloat16(f0 - __bfloat162float(h0));
        __nv_bfloat16 l1 = __float2bfloat16(f1 - __bfloat162float(h1));
        __nv_bfloat16 l2 = __float2bfloat16(f2 - __bfloat162float(h2));
        __nv_bfloat16 l3 = __float2bfloat16(f3 - __bfloat162float(h3));
        __nv_bfloat162 hh0{h0, h1}, hh1{h2, h3}, ll0{l0, l1}, ll1{l2, l3};
        reinterpret_cast<__nv_bfloat162*>(hi)[i4 * 2 + 0] = hh0;
        reinterpret_cast<__nv_bfloat162*>(hi)[i4 * 2 + 1] = hh1;
        reinterpret_cast<__nv_bfloat162*>(lo)[i4 * 2 + 0] = ll0;
        reinterpret_cast<__nv_bfloat162*>(lo)[i4 * 2 + 1] = ll1;
    }
}

// ---------------- launch ----------------------------------------------------
extern "C" void kernel_launch(void* const* d_in, const int* in_sizes, int n_in,
                              void* d_out, int out_size)
{
    const float* x          = (const float*)d_in[0];
    const float* in_proj_w  = (const float*)d_in[1];
    const float* conv_w     = (const float*)d_in[2];
    const float* conv_b     = (const float*)d_in[3];
    const float* A_log      = (const float*)d_in[4];
    const float* D_param    = (const float*)d_in[5];
    const float* dt_bias    = (const float*)d_in[6];
    const float* norm_w     = (const float*)d_in[7];
    const float* out_proj_w = (const float*)d_in[8];
    float* out = (float*)d_out;

    float *p_zx;
    __nv_bfloat16 *p_xhi, *p_xlo, *p_w1hi, *p_w1lo, *p_yhi, *p_ylo, *p_w2hi, *p_w2lo;
    cudaGetSymbolAddress((void**)&p_zx,   g_zx);
    cudaGetSymbolAddress((void**)&p_xhi,  g_xhi);
    cudaGetSymbolAddress((void**)&p_xlo,  g_xlo);
    cudaGetSymbolAddress((void**)&p_w1hi, g_w1hi);
    cudaGetSymbolAddress((void**)&p_w1lo, g_w1lo);
    cudaGetSymbolAddress((void**)&p_yhi,  g_yhi);
    cudaGetSymbolAddress((void**)&p_ylo,  g_ylo);
    cudaGetSymbolAddress((void**)&p_w2hi, g_w2hi);
    cudaGetSymbolAddress((void**)&p_w2lo, g_w2lo);

    const int dyn_smem = 12 * TSZ;   // 192KB (3 stages)
    cudaFuncSetAttribute(gemm_mma, cudaFuncAttributeMaxDynamicSharedMemorySize, dyn_smem);

    // 0. split all fp32 inputs to bf16 hi/lo (one launch)
    {
        int total = N4X + N4W1 + N4W2;
        split_all<<<(total + 255) / 256, 256>>>(x, in_proj_w, out_proj_w);
    }
    // 1. in_proj
    {
        dim3 grid((D_IN_PROJ + 127) / 128, ML / 128);
        gemm_mma<<<grid, 256, dyn_smem>>>(p_xhi, p_xlo, p_w1hi, p_w1lo,
                                          p_zx, ML, D_IN_PROJ, DIMM);
    }
    // 2. conv + silu (+ a_bar fused)
    conv_silu_abar_kernel<<<(ML * D_INNER) / 256, 256>>>(conv_w, conv_b, A_log, dt_bias);
    // 3. segment decay products (parallel)
    aseg_kernel<<<16, 256>>>();
    // 4. two-level scan (combine inlined into pass C)
    scan_partA<<<1024, 128>>>();
    scan_partC<<<1024, 128>>>(D_param);
    // 5. rmsnorm + y split fused
    rmsnorm_split_kernel<<<ML, 256>>>(norm_w);
    // 6. out_proj
    {
        dim3 grid(DIMM / 128, ML / 128);
        gemm_mma<<<grid, 256, dyn_smem>>>(p_yhi, p_ylo, p_w2hi, p_w2lo,
                                          out, ML, DIMM, D_INNER);
    }
}